// round 12
// baseline (speedup 1.0000x reference)
#include <cuda_runtime.h>
#include <math.h>

#define BB 4
#define NN 4096
#define KK 20
#define NPTS (BB*NN)            // 16384
#define EDG  (NPTS*KK)          // 327680
#define STATS_BLOCKS 512
#define FULLM 0xffffffffu

#define FINF __int_as_float(0x7f800000)
#define ULLMAX 0xFFFFFFFFFFFFFFFFULL

// ---------------- scratch (device globals; no allocations allowed) ----------
__device__ float g_dist[(size_t)BB * NN * NN];      // float distances (layer 1)
__device__ float4 g_x4[NPTS];                        // packed (x,y,z,|x|^2)
__device__ float g_d2[NPTS];
__device__ int   g_idx[NPTS * KK];
__device__ float g_u[NPTS * 256];
__device__ float g_v[NPTS * 256];
__device__ float g_vmax[NPTS * 256];
__device__ float g_vmin[NPTS * 256];
__device__ float g_h0[NPTS * 64];
__device__ float g_h1[NPTS * 256];
__device__ float g_Wd0[3 * 64];
__device__ float g_Wd1[64 * 256];
__device__ float g_part[STATS_BLOCKS * 2 * 256];
__device__ float g_scale[256];
__device__ float g_shift[256];
__device__ float g_gate[NPTS];
__device__ float g_alpha[NPTS];
__device__ float g_pool[32 * BB * 512];
__device__ float g_pooled[BB * 512];

static __device__ __forceinline__ float leaky(float v) { return v > 0.f ? v : 0.2f * v; }

// float -> order-preserving uint (ascending float == ascending uint)
static __device__ __forceinline__ unsigned okey(float f) {
    unsigned u = __float_as_uint(f);
    return u ^ ((unsigned)(((int)u) >> 31) | 0x80000000u);
}

// ---------------- packed fp32x2 helpers (sm_103a) -----------------------------
static __device__ __forceinline__ unsigned long long pk2(float lo, float hi) {
    unsigned long long r;
    asm("mov.b64 %0, {%1, %2};" : "=l"(r) : "f"(lo), "f"(hi));
    return r;
}
static __device__ __forceinline__ void fma2(unsigned long long& acc,
                                            unsigned long long a,
                                            unsigned long long b) {
    asm("fma.rn.f32x2 %0, %1, %2, %0;" : "+l"(acc) : "l"(a), "l"(b));
}
static __device__ __forceinline__ float2 upk2(unsigned long long v) {
    float lo, hi;
    asm("mov.b64 {%0, %1}, %2;" : "=f"(lo), "=f"(hi) : "l"(v));
    return make_float2(lo, hi);
}

// ---------------- warp bitonic sorts ------------------------------------------
template <int NR>
static __device__ __forceinline__ void wsortf(float* v, int lane) {
    const int N = NR * 32;
    #pragma unroll
    for (int k = 2; k <= N; k <<= 1) {
        #pragma unroll
        for (int j = k >> 1; j > 0; j >>= 1) {
            if (j >= 32) {
                int rj = j >> 5;
                #pragma unroll
                for (int rr = 0; rr < NR; rr++) {
                    int pr = rr ^ rj;
                    if (pr > rr) {
                        int p = rr * 32 + lane;
                        bool asc = ((p & k) == 0);
                        float a = v[rr], b = v[pr];
                        float mn = fminf(a, b), mx = fmaxf(a, b);
                        v[rr] = asc ? mn : mx;
                        v[pr] = asc ? mx : mn;
                    }
                }
            } else {
                #pragma unroll
                for (int rr = 0; rr < NR; rr++) {
                    int p = rr * 32 + lane;
                    bool asc = ((p & k) == 0);
                    bool lower = ((lane & j) == 0);
                    float o = __shfl_xor_sync(FULLM, v[rr], j);
                    bool keepmin = (asc == lower);
                    float mn = fminf(v[rr], o), mx = fmaxf(v[rr], o);
                    v[rr] = keepmin ? mn : mx;
                }
            }
        }
    }
}

template <int NR>
static __device__ __forceinline__ void wsortu64(unsigned long long* v, int lane) {
    const int N = NR * 32;
    #pragma unroll
    for (int k = 2; k <= N; k <<= 1) {
        #pragma unroll
        for (int j = k >> 1; j > 0; j >>= 1) {
            if (j >= 32) {
                int rj = j >> 5;
                #pragma unroll
                for (int rr = 0; rr < NR; rr++) {
                    int pr = rr ^ rj;
                    if (pr > rr) {
                        int p = rr * 32 + lane;
                        bool asc = ((p & k) == 0);
                        unsigned long long a = v[rr], b = v[pr];
                        unsigned long long mn = a < b ? a : b;
                        unsigned long long mx = a < b ? b : a;
                        v[rr] = asc ? mn : mx;
                        v[pr] = asc ? mx : mn;
                    }
                }
            } else {
                #pragma unroll
                for (int rr = 0; rr < NR; rr++) {
                    int p = rr * 32 + lane;
                    bool asc = ((p & k) == 0);
                    bool lower = ((lane & j) == 0);
                    unsigned long long o = __shfl_xor_sync(FULLM, v[rr], j);
                    bool keepmin = (asc == lower);
                    unsigned long long mn = v[rr] < o ? v[rr] : o;
                    unsigned long long mx = v[rr] < o ? o : v[rr];
                    v[rr] = keepmin ? mn : mx;
                }
            }
        }
    }
}

// ---------------- fallback streaming top-32 (exact, rare) --------------------
static __device__ __forceinline__ unsigned long long wmax64(unsigned long long m) {
    #pragma unroll
    for (int o = 16; o; o >>= 1) {
        unsigned long long ov = __shfl_xor_sync(FULLM, m, o);
        m = m > ov ? m : ov;
    }
    return m;
}

static __device__ __forceinline__ void winsert(unsigned long long c,
                                               unsigned long long& sc,
                                               unsigned long long& tau,
                                               int lane) {
    unsigned bal = __ballot_sync(FULLM, c < tau);
    while (bal) {
        int src = __ffs(bal) - 1;
        bal &= bal - 1;
        unsigned long long cn = __shfl_sync(FULLM, c, src);
        if (cn < tau) {
            unsigned eq = __ballot_sync(FULLM, sc == tau);
            if (lane == __ffs(eq) - 1) sc = cn;
            tau = wmax64(sc);
        }
    }
}

static __device__ __forceinline__ void wfinish(unsigned long long sc, int lane, int* out) {
    unsigned long long v1[1] = {sc};
    wsortu64<1>(v1, lane);
    if (lane < KK) out[lane] = (int)(v1[0] & 0xffffffffu);
}

// sort <=128 composites already in smem buf, emit KK indices
static __device__ __forceinline__ bool buf_finish(unsigned long long* bufw, int cnt,
                                                  int lane, int* out) {
    if (cnt > 128) return false;
    if (cnt <= 64) {
        unsigned long long e[2];
        e[0] = (lane < cnt) ? bufw[lane] : ULLMAX;
        e[1] = (lane + 32 < cnt) ? bufw[lane + 32] : ULLMAX;
        wsortu64<2>(e, lane);
        if (lane < KK) out[lane] = (int)(e[0] & 0xffffffffu);
    } else {
        unsigned long long e[4];
        #pragma unroll
        for (int rr = 0; rr < 4; rr++)
            e[rr] = (rr * 32 + lane < cnt) ? bufw[rr * 32 + lane] : ULLMAX;
        wsortu64<4>(e, lane);
        if (lane < KK) out[lane] = (int)(e[0] & 0xffffffffu);
    }
    return true;
}

// ---------------- weight prep: Wd = Wp - Wt ---------------------------------
__global__ void prep_k(const float* __restrict__ Wt0, const float* __restrict__ Wp0,
                       const float* __restrict__ Wt1, const float* __restrict__ Wp1) {
    int i = blockIdx.x * 256 + threadIdx.x;
    if (i < 192) g_Wd0[i] = Wp0[i] - Wt0[i];
    int j = i - 192;
    if (j >= 0 && j < 16384) g_Wd1[j] = Wp1[j] - Wt1[j];
}

// ---------------- pack x + squared norm --------------------------------------
__global__ void pack3_k(const float* __restrict__ x) {
    int r = blockIdx.x * blockDim.x + threadIdx.x;
    if (r >= NPTS) return;
    float a = x[r * 3], b = x[r * 3 + 1], c = x[r * 3 + 2];
    g_x4[r] = make_float4(a, b, c, a * a + b * b + c * c);
}

__global__ void norms64_k() {
    int gt = blockIdx.x * blockDim.x + threadIdx.x;
    int r = gt >> 5, lane = gt & 31;
    if (r >= NPTS) return;
    const float* h = g_h0 + (size_t)r * 64;
    float a = h[lane], b = h[lane + 32];
    float s = a * a + b * b;
    #pragma unroll
    for (int o = 16; o; o >>= 1) s += __shfl_down_sync(FULLM, s, o);
    if (lane == 0) g_d2[r] = s;
}

// ---------------- layer0 u/v (3->64, trivial) --------------------------------
__global__ void uv0_k(const float* __restrict__ x, const float* __restrict__ Wt0) {
    int gid = blockIdx.x * 256 + threadIdx.x;   // NPTS*64 total
    int r = gid >> 6, c = gid & 63;
    float x0 = x[r * 3], x1 = x[r * 3 + 1], x2 = x[r * 3 + 2];
    g_u[gid] = x0 * Wt0[c] + x1 * Wt0[64 + c] + x2 * Wt0[128 + c];
    g_v[gid] = x0 * g_Wd0[c] + x1 * g_Wd0[64 + c] + x2 * g_Wd0[128 + c];
}

// ---------------- fused 16-row (64->256) GEMM, f32x2 packed ------------------
__global__ __launch_bounds__(256) void gemm16_k(const float* __restrict__ Wt1) {
    __shared__ float hs[16 * 64];
    int r0 = blockIdx.x * 16;
    int t = threadIdx.x;
    #pragma unroll
    for (int s = 0; s < 4; s++) {
        int l = t + (s << 8);
        hs[l] = g_h0[(size_t)r0 * 64 + l];
    }
    __syncthreads();
    unsigned long long au2[16], av2[16];
    #pragma unroll
    for (int r = 0; r < 16; r++) { au2[r] = 0ull; av2[r] = 0ull; }
    #pragma unroll 4
    for (int d = 0; d < 64; d += 2) {
        unsigned long long wu = pk2(Wt1[d * 256 + t], Wt1[(d + 1) * 256 + t]);
        unsigned long long wv = pk2(g_Wd1[d * 256 + t], g_Wd1[(d + 1) * 256 + t]);
        #pragma unroll
        for (int r = 0; r < 16; r++) {
            float2 h2 = *(const float2*)&hs[r * 64 + d];
            unsigned long long hp = pk2(h2.x, h2.y);
            fma2(au2[r], hp, wu);
            fma2(av2[r], hp, wv);
        }
    }
    #pragma unroll
    for (int r = 0; r < 16; r++) {
        float2 su = upk2(au2[r]);
        float2 sv = upk2(av2[r]);
        g_u[(size_t)(r0 + r) * 256 + t] = su.x + su.y;
        g_v[(size_t)(r0 + r) * 256 + t] = sv.x + sv.y;
    }
}

// ---------------- distance GEMM (layer1), triangular grid, f32x2 -------------
static __device__ __forceinline__ int tri_start(int ti) {
    return ti * 64 - (ti * (ti - 1)) / 2;
}

__global__ __launch_bounds__(256) void dist_gemm_k() {
    const int b = blockIdx.y;
    int l = blockIdx.x;                    // 0..2079
    int ti = (int)((129.0f - sqrtf(129.0f * 129.0f - 8.0f * (float)l)) * 0.5f);
    if (ti > 63) ti = 63;
    while (ti < 63 && tri_start(ti + 1) <= l) ti++;
    while (ti > 0 && tri_start(ti) > l) ti--;
    int tj = ti + (l - tri_start(ti));
    const int i0 = ti * 64, j0 = tj * 64;
    __shared__ float As[64][68];   // 272B rows -> 16B-aligned float4
    __shared__ float Bs[64][68];
    const float* hb = g_h0 + (size_t)b * NN * 64;
    int t = threadIdx.x;
    #pragma unroll
    for (int s = 0; s < 16; s++) {
        int ll = t + (s << 8);
        int r = ll >> 6, d = ll & 63;
        As[d][r] = hb[(size_t)(i0 + r) * 64 + d];
        Bs[d][r] = hb[(size_t)(j0 + r) * 64 + d];
    }
    __syncthreads();
    int tx = t & 15, ty = t >> 4;
    unsigned long long acc2[4][2];   // [row][col-pair], bit-exact column sums
    #pragma unroll
    for (int r = 0; r < 4; r++) { acc2[r][0] = 0ull; acc2[r][1] = 0ull; }
    #pragma unroll 8
    for (int d = 0; d < 64; d++) {
        float4 av = *(const float4*)&As[d][ty * 4];
        float4 bv = *(const float4*)&Bs[d][tx * 4];
        unsigned long long b01 = pk2(bv.x, bv.y);
        unsigned long long b23 = pk2(bv.z, bv.w);
        unsigned long long a0 = pk2(av.x, av.x);
        unsigned long long a1 = pk2(av.y, av.y);
        unsigned long long a2 = pk2(av.z, av.z);
        unsigned long long a3 = pk2(av.w, av.w);
        fma2(acc2[0][0], a0, b01); fma2(acc2[0][1], a0, b23);
        fma2(acc2[1][0], a1, b01); fma2(acc2[1][1], a1, b23);
        fma2(acc2[2][0], a2, b01); fma2(acc2[2][1], a2, b23);
        fma2(acc2[3][0], a3, b01); fma2(acc2[3][1], a3, b23);
    }
    const float* n2 = g_d2 + b * NN;
    float nj0 = n2[j0 + tx * 4 + 0], nj1 = n2[j0 + tx * 4 + 1];
    float nj2 = n2[j0 + tx * 4 + 2], nj3 = n2[j0 + tx * 4 + 3];
    float ov[4][4];
    #pragma unroll
    for (int r = 0; r < 4; r++) {
        float ni = n2[i0 + ty * 4 + r];
        float2 p01 = upk2(acc2[r][0]);
        float2 p23 = upk2(acc2[r][1]);
        ov[r][0] = ni + nj0 - 2.f * p01.x;
        ov[r][1] = ni + nj1 - 2.f * p01.y;
        ov[r][2] = ni + nj2 - 2.f * p23.x;
        ov[r][3] = ni + nj3 - 2.f * p23.y;
        *(float4*)&g_dist[((size_t)(b * NN + i0 + ty * 4 + r)) * NN + j0 + tx * 4] =
            make_float4(ov[r][0], ov[r][1], ov[r][2], ov[r][3]);
    }
    if (ti != tj) {
        __syncthreads();
        float* Ts = &As[0][0];                 // reuse [64][68]
        #pragma unroll
        for (int r = 0; r < 4; r++)
            #pragma unroll
            for (int c = 0; c < 4; c++)
                Ts[(tx * 4 + c) * 68 + (ty * 4 + r)] = ov[r][c];
        __syncthreads();
        #pragma unroll
        for (int s = 0; s < 16; s++) {
            int ll = t + (s << 8);
            int jr = ll >> 6, ic = ll & 63;
            g_dist[((size_t)(b * NN + j0 + jr)) * NN + i0 + ic] = Ts[jr * 68 + ic];
        }
    }
}

// ---------------- knn0: f32 pass1 + ballot-compact pass2 ---------------------
__global__ __launch_bounds__(256) void knn0_k() {
    __shared__ float4 pts[1024];                    // 16 KB
    __shared__ unsigned long long buf[8][128];      // 8 KB
    int t = threadIdx.x, w = t >> 5, lane = t & 31;
    int row = blockIdx.x * 8 + w;
    int base = row & ~(NN - 1);
    float4 me = g_x4[row];

    // pass 1: per-lane top-2 float distances (fma pipe)
    float m0 = FINF, m1 = FINF;
    #pragma unroll 1
    for (int chunk = 0; chunk < 4; chunk++) {
        __syncthreads();
        #pragma unroll
        for (int i = 0; i < 4; i++)
            pts[t + (i << 8)] = g_x4[base + (chunk << 10) + t + (i << 8)];
        __syncthreads();
        #pragma unroll 4
        for (int it = 0; it < 32; it++) {
            float4 p = pts[(it << 5) + lane];
            float dot = me.x * p.x + me.y * p.y + me.z * p.z;
            float d = me.w + p.w - 2.f * dot;
            if (d < m0) { m1 = m0; m0 = d; }
            else if (d < m1) { m1 = d; }
        }
    }
    float v2[2] = {m0, m1};
    wsortf<2>(v2, lane);
    float tau = __shfl_sync(FULLM, v2[0], 31);   // 32nd smallest collected

    // pass 2: ballot-compact composites of all d <= tau
    int cnt = 0;
    #pragma unroll 1
    for (int chunk = 0; chunk < 4; chunk++) {
        __syncthreads();
        #pragma unroll
        for (int i = 0; i < 4; i++)
            pts[t + (i << 8)] = g_x4[base + (chunk << 10) + t + (i << 8)];
        __syncthreads();
        #pragma unroll 4
        for (int it = 0; it < 32; it++) {
            int jl = (it << 5) + lane;
            float4 p = pts[jl];
            float dot = me.x * p.x + me.y * p.y + me.z * p.z;
            float d = me.w + p.w - 2.f * dot;
            unsigned mask = __ballot_sync(FULLM, d <= tau);
            if (d <= tau) {
                int pos = cnt + __popc(mask & ((1u << lane) - 1));
                if (pos < 128)
                    buf[w][pos] = ((unsigned long long)okey(d) << 32)
                                | (unsigned)((chunk << 10) + jl);
            }
            cnt += __popc(mask);
        }
    }
    int* out = g_idx + row * KK;
    if (!buf_finish(buf[w], cnt, lane, out)) {
        // exact streaming fallback (degenerate ties)
        unsigned long long sc, tau2;
        {
            float4 p = g_x4[base + lane];
            float dot = me.x * p.x + me.y * p.y + me.z * p.z;
            float d = me.w + p.w - 2.f * dot;
            sc = ((unsigned long long)okey(d) << 32) | (unsigned)lane;
            tau2 = wmax64(sc);
        }
        for (int it = 1; it < 128; it++) {
            int j = (it << 5) + lane;
            float4 p = g_x4[base + j];
            float dot = me.x * p.x + me.y * p.y + me.z * p.z;
            float d = me.w + p.w - 2.f * dot;
            unsigned long long c = ((unsigned long long)okey(d) << 32) | (unsigned)j;
            winsert(c, sc, tau2, lane);
        }
        wfinish(sc, lane, out);
    }
}

// ---------------- knn1: f32 pass1 + ballot-compact pass2 over dist rows ------
__global__ __launch_bounds__(256) void knn1_k() {
    __shared__ unsigned long long buf[8][128];      // 8 KB
    int t = threadIdx.x, w = t >> 5, lane = t & 31;
    int row = blockIdx.x * 8 + w;
    const float4* dr = (const float4*)(g_dist + (size_t)row * NN);   // 1024 float4

    // pass 1
    float m0 = FINF, m1 = FINF;
    #pragma unroll 4
    for (int it = 0; it < 32; it++) {
        float4 dv = __ldg(&dr[(it << 5) + lane]);
        if (dv.x < m0) { m1 = m0; m0 = dv.x; } else if (dv.x < m1) m1 = dv.x;
        if (dv.y < m0) { m1 = m0; m0 = dv.y; } else if (dv.y < m1) m1 = dv.y;
        if (dv.z < m0) { m1 = m0; m0 = dv.z; } else if (dv.z < m1) m1 = dv.z;
        if (dv.w < m0) { m1 = m0; m0 = dv.w; } else if (dv.w < m1) m1 = dv.w;
    }
    float v2[2] = {m0, m1};
    wsortf<2>(v2, lane);
    float tau = __shfl_sync(FULLM, v2[0], 31);

    // pass 2 (row L1-resident)
    int cnt = 0;
    #pragma unroll 2
    for (int it = 0; it < 32; it++) {
        int j4 = (it << 5) + lane;
        float4 dv = __ldg(&dr[j4]);
        int jb = j4 << 2;
        float ds[4] = {dv.x, dv.y, dv.z, dv.w};
        #pragma unroll
        for (int q = 0; q < 4; q++) {
            float d = ds[q];
            unsigned mask = __ballot_sync(FULLM, d <= tau);
            if (d <= tau) {
                int pos = cnt + __popc(mask & ((1u << lane) - 1));
                if (pos < 128)
                    buf[w][pos] = ((unsigned long long)okey(d) << 32) | (unsigned)(jb + q);
            }
            cnt += __popc(mask);
        }
    }
    int* out = g_idx + row * KK;
    if (!buf_finish(buf[w], cnt, lane, out)) {
        const float* drs = g_dist + (size_t)row * NN;
        unsigned long long sc, tau2;
        {
            sc = ((unsigned long long)okey(drs[lane]) << 32) | (unsigned)lane;
            tau2 = wmax64(sc);
        }
        for (int it = 1; it < 128; it++) {
            int j = (it << 5) + lane;
            unsigned long long c = ((unsigned long long)okey(__ldg(&drs[j])) << 32) | (unsigned)j;
            winsert(c, sc, tau2, lane);
        }
        wfinish(sc, lane, out);
    }
}

// ---------------- fused gather: BN stats + per-point neighbor vmax/vmin ------
template <int C>
__global__ __launch_bounds__(256) void gather_k() {
    constexpr int G = 256 / C;
    int t = threadIdx.x;
    int c = t % C;
    int g = t / C;
    float s = 0.f, s2 = 0.f;
    for (int p = blockIdx.x * G + g; p < NPTS; p += STATS_BLOCKS * G) {
        int b = p >> 12;
        float uc = g_u[(size_t)p * C + c];
        const int* ip = g_idx + p * KK;
        float S = 0.f, Q = 0.f, mx = -FINF, mn = FINF;
        #pragma unroll
        for (int k = 0; k < KK; k++) {
            int j = ip[k];
            float v = g_v[((size_t)((b << 12) + j)) * C + c];
            S += v;
            Q = fmaf(v, v, Q);
            mx = fmaxf(mx, v);
            mn = fminf(mn, v);
        }
        g_vmax[(size_t)p * C + c] = mx;
        g_vmin[(size_t)p * C + c] = mn;
        s += fmaf(20.f, uc, S);
        s2 += fmaf(20.f * uc, uc, fmaf(2.f * uc, S, Q));
    }
    __shared__ float sh[256], sh2[256];
    sh[t] = s; sh2[t] = s2;
    __syncthreads();
    if (t < C) {
        float S = sh[t], S2 = sh2[t];
        #pragma unroll
        for (int gg = 1; gg < G; gg++) { S += sh[gg * C + t]; S2 += sh2[gg * C + t]; }
        g_part[blockIdx.x * (2 * C) + t] = S;
        g_part[blockIdx.x * (2 * C) + C + t] = S2;
    }
}

template <int C>
__global__ void fin_k(const float* __restrict__ gamma, const float* __restrict__ beta) {
    int c = threadIdx.x;
    float S = 0.f, S2 = 0.f;
    for (int bk = 0; bk < STATS_BLOCKS; bk++) {
        S += g_part[bk * 2 * C + c];
        S2 += g_part[bk * 2 * C + C + c];
    }
    const float inv = 1.f / (float)EDG;
    float mu = S * inv;
    float var = S2 * inv - mu * mu;
    float sc = gamma[c] * rsqrtf(var + 1e-5f);
    g_scale[c] = sc;
    g_shift[c] = beta[c] - mu * sc;
}

// ---------------- finish: h = leaky(scale*(u + vmax/vmin) + shift) -----------
template <int C>
__global__ void finish_k() {
    int gid = blockIdx.x * 256 + threadIdx.x;    // NPTS*C
    int c = gid & (C - 1);
    float sc = g_scale[c];
    float vm = (sc >= 0.f) ? g_vmax[gid] : g_vmin[gid];
    float M = g_u[gid] + vm;
    float* out = (C == 64) ? (float*)g_h0 : (float*)g_h1;
    out[gid] = leaky(fmaf(M, sc, g_shift[c]));
}

// ---------------- attention gate + softmax -----------------------------------
__global__ void gate_k(const float* __restrict__ Wg, const float* __restrict__ bg) {
    int gt = blockIdx.x * 256 + threadIdx.x;
    int r = gt >> 5, lane = gt & 31;
    if (r >= NPTS) return;
    const float* h = g_h1 + (size_t)r * 256;
    float s = 0.f;
    #pragma unroll
    for (int q = 0; q < 8; q++) {
        int d = lane + (q << 5);
        s = fmaf(h[d], Wg[d], s);
    }
    #pragma unroll
    for (int o = 16; o; o >>= 1) s += __shfl_down_sync(FULLM, s, o);
    if (lane == 0) {
        float gg = s + bg[0];
        g_gate[r] = gg > 0.f ? gg : 0.f;
    }
}

__global__ void softmax_k() {
    int b = blockIdx.x, t = threadIdx.x;
    __shared__ float sh[256];
    const float* gp = g_gate + (b << 12);
    float* ap = g_alpha + (b << 12);
    float mx = -FINF;
    for (int s = 0; s < 16; s++) mx = fmaxf(mx, gp[t + (s << 8)]);
    sh[t] = mx; __syncthreads();
    for (int o = 128; o; o >>= 1) { if (t < o) sh[t] = fmaxf(sh[t], sh[t + o]); __syncthreads(); }
    float M = sh[0];
    __syncthreads();
    float sum = 0.f;
    for (int s = 0; s < 16; s++) {
        int j = t + (s << 8);
        float e = expf(gp[j] - M);
        ap[j] = e;
        sum += e;
    }
    sh[t] = sum; __syncthreads();
    for (int o = 128; o; o >>= 1) { if (t < o) sh[t] += sh[t + o]; __syncthreads(); }
    float inv = 1.f / sh[0];
    for (int s = 0; s < 16; s++) ap[t + (s << 8)] *= inv;
}

// ---------------- fused feat GEMM + weighted pooling (f32x2) ------------------
__global__ __launch_bounds__(256) void pool_k(const float* __restrict__ Wf,
                                              const float* __restrict__ bf) {
    int b = blockIdx.x;
    int t = threadIdx.x;
    int ch = blockIdx.y * 256 + t;
    int slab = blockIdx.z;
    __shared__ float hr[16][256];
    __shared__ float al[16];
    float acc = 0.f;
    float bfc = bf[ch];
    for (int gidx = 0; gidx < 8; gidx++) {
        int nb = (slab << 7) + (gidx << 4);
        __syncthreads();
        #pragma unroll
        for (int s = 0; s < 16; s++)
            hr[s][t] = g_h1[((size_t)(b << 12) + nb + s) * 256 + t];
        if (t < 16) al[t] = g_alpha[(b << 12) + nb + t];
        __syncthreads();
        unsigned long long sacc2[16];
        #pragma unroll
        for (int r = 0; r < 16; r++) sacc2[r] = 0ull;
        #pragma unroll 4
        for (int d = 0; d < 256; d += 4) {
            unsigned long long w01 = pk2(Wf[(d + 0) * 512 + ch], Wf[(d + 1) * 512 + ch]);
            unsigned long long w23 = pk2(Wf[(d + 2) * 512 + ch], Wf[(d + 3) * 512 + ch]);
            #pragma unroll
            for (int r = 0; r < 16; r++) {
                float4 hv = *(const float4*)&hr[r][d];
                fma2(sacc2[r], pk2(hv.x, hv.y), w01);
                fma2(sacc2[r], pk2(hv.z, hv.w), w23);
            }
        }
        #pragma unroll
        for (int r = 0; r < 16; r++) {
            float2 sp = upk2(sacc2[r]);
            float f = sp.x + sp.y + bfc;
            f = f > 0.f ? f : 0.f;
            acc = fmaf(al[r], f, acc);
        }
    }
    g_pool[((slab << 2) + b) * 512 + ch] = acc;
}

__global__ void poolred_k() {
    int gid = blockIdx.x * 256 + threadIdx.x;  // BB*512
    if (gid >= BB * 512) return;
    int b = gid >> 9, ch = gid & 511;
    float s = 0.f;
    for (int sl = 0; sl < 32; sl++) s += g_pool[((sl << 2) + b) * 512 + ch];
    g_pooled[gid] = s;
}

__global__ void final_k(const float* __restrict__ Wl, const float* __restrict__ bl,
                        float* __restrict__ out) {
    int b = blockIdx.x, o = threadIdx.x;
    const float* p = g_pooled + b * 512;
    float s = bl[o];
    #pragma unroll 8
    for (int f = 0; f < 512; f++) s = fmaf(p[f], Wl[f * 256 + o], s);
    out[b * 256 + o] = s;
}

// ---------------- launch ------------------------------------------------------
extern "C" void kernel_launch(void* const* d_in, const int* in_sizes, int n_in,
                              void* d_out, int out_size) {
    (void)in_sizes; (void)n_in; (void)out_size;
    const float* x   = (const float*)d_in[0];
    const float* Wt0 = (const float*)d_in[1];
    const float* Wp0 = (const float*)d_in[3];
    const float* g0  = (const float*)d_in[5];
    const float* be0 = (const float*)d_in[6];
    const float* Wt1 = (const float*)d_in[7];
    const float* Wp1 = (const float*)d_in[9];
    const float* g1  = (const float*)d_in[11];
    const float* be1 = (const float*)d_in[12];
    const float* Wg  = (const float*)d_in[13];
    const float* bg  = (const float*)d_in[14];
    const float* Wf  = (const float*)d_in[15];
    const float* bf  = (const float*)d_in[16];
    const float* Wl  = (const float*)d_in[17];
    const float* bl  = (const float*)d_in[18];
    float* out = (float*)d_out;

    // ---- layer 0 ----
    prep_k<<<65, 256>>>(Wt0, Wp0, Wt1, Wp1);
    pack3_k<<<64, 256>>>(x);
    uv0_k<<<NPTS * 64 / 256, 256>>>(x, Wt0);
    knn0_k<<<NPTS / 8, 256>>>();
    gather_k<64><<<STATS_BLOCKS, 256>>>();
    fin_k<64><<<1, 64>>>(g0, be0);
    finish_k<64><<<NPTS * 64 / 256, 256>>>();

    // ---- layer 1 ----
    norms64_k<<<NPTS * 32 / 256, 256>>>();
    gemm16_k<<<NPTS / 16, 256>>>(Wt1);
    dist_gemm_k<<<dim3(2080, BB), 256>>>();
    knn1_k<<<NPTS / 8, 256>>>();
    gather_k<256><<<STATS_BLOCKS, 256>>>();
    fin_k<256><<<1, 256>>>(g1, be1);
    finish_k<256><<<NPTS * 256 / 256, 256>>>();

    // ---- attention pooling + final linear ----
    gate_k<<<NPTS * 32 / 256, 256>>>(Wg, bg);
    softmax_k<<<BB, 256>>>();
    pool_k<<<dim3(BB, 2, 32), 256>>>(Wf, bf);
    poolred_k<<<8, 256>>>();
    final_k<<<BB, 256>>>(Wl, bl, out);
}

// round 13
// speedup vs baseline: 1.0203x; 1.0203x over previous
#include <cuda_runtime.h>
#include <math.h>

#define BB 4
#define NN 4096
#define KK 20
#define NPTS (BB*NN)            // 16384
#define EDG  (NPTS*KK)          // 327680
#define STATS_BLOCKS 512
#define FULLM 0xffffffffu

#define FINF __int_as_float(0x7f800000)
#define ULLMAX 0xFFFFFFFFFFFFFFFFULL

// ---------------- scratch (device globals; no allocations allowed) ----------
__device__ float g_dist[(size_t)BB * NN * NN];      // float distances (layer 1)
__device__ float4 g_x4[NPTS];                        // packed (x,y,z,|x|^2)
__device__ float g_d2[NPTS];
__device__ int   g_idx[NPTS * KK];
__device__ float g_u[NPTS * 256];
__device__ float g_v[NPTS * 256];
__device__ float g_vmax[NPTS * 256];
__device__ float g_vmin[NPTS * 256];
__device__ float g_h0[NPTS * 64];
__device__ float g_h1[NPTS * 256];
__device__ float g_Wd1[64 * 256];
__device__ float g_part[STATS_BLOCKS * 2 * 256];
__device__ float g_scale[256];
__device__ float g_shift[256];
__device__ float g_gate[NPTS];
__device__ float g_alpha[NPTS];
__device__ float g_pool[32 * BB * 512];
__device__ float g_pooled[BB * 512];

static __device__ __forceinline__ float leaky(float v) { return v > 0.f ? v : 0.2f * v; }

// float -> order-preserving uint (ascending float == ascending uint)
static __device__ __forceinline__ unsigned okey(float f) {
    unsigned u = __float_as_uint(f);
    return u ^ ((unsigned)(((int)u) >> 31) | 0x80000000u);
}

// ---------------- warp bitonic sorts ------------------------------------------
template <int NR>
static __device__ __forceinline__ void wsortf(float* v, int lane) {
    const int N = NR * 32;
    #pragma unroll
    for (int k = 2; k <= N; k <<= 1) {
        #pragma unroll
        for (int j = k >> 1; j > 0; j >>= 1) {
            if (j >= 32) {
                int rj = j >> 5;
                #pragma unroll
                for (int rr = 0; rr < NR; rr++) {
                    int pr = rr ^ rj;
                    if (pr > rr) {
                        int p = rr * 32 + lane;
                        bool asc = ((p & k) == 0);
                        float a = v[rr], b = v[pr];
                        float mn = fminf(a, b), mx = fmaxf(a, b);
                        v[rr] = asc ? mn : mx;
                        v[pr] = asc ? mx : mn;
                    }
                }
            } else {
                #pragma unroll
                for (int rr = 0; rr < NR; rr++) {
                    int p = rr * 32 + lane;
                    bool asc = ((p & k) == 0);
                    bool lower = ((lane & j) == 0);
                    float o = __shfl_xor_sync(FULLM, v[rr], j);
                    bool keepmin = (asc == lower);
                    float mn = fminf(v[rr], o), mx = fmaxf(v[rr], o);
                    v[rr] = keepmin ? mn : mx;
                }
            }
        }
    }
}

template <int NR>
static __device__ __forceinline__ void wsortu64(unsigned long long* v, int lane) {
    const int N = NR * 32;
    #pragma unroll
    for (int k = 2; k <= N; k <<= 1) {
        #pragma unroll
        for (int j = k >> 1; j > 0; j >>= 1) {
            if (j >= 32) {
                int rj = j >> 5;
                #pragma unroll
                for (int rr = 0; rr < NR; rr++) {
                    int pr = rr ^ rj;
                    if (pr > rr) {
                        int p = rr * 32 + lane;
                        bool asc = ((p & k) == 0);
                        unsigned long long a = v[rr], b = v[pr];
                        unsigned long long mn = a < b ? a : b;
                        unsigned long long mx = a < b ? b : a;
                        v[rr] = asc ? mn : mx;
                        v[pr] = asc ? mx : mn;
                    }
                }
            } else {
                #pragma unroll
                for (int rr = 0; rr < NR; rr++) {
                    int p = rr * 32 + lane;
                    bool asc = ((p & k) == 0);
                    bool lower = ((lane & j) == 0);
                    unsigned long long o = __shfl_xor_sync(FULLM, v[rr], j);
                    bool keepmin = (asc == lower);
                    unsigned long long mn = v[rr] < o ? v[rr] : o;
                    unsigned long long mx = v[rr] < o ? o : v[rr];
                    v[rr] = keepmin ? mn : mx;
                }
            }
        }
    }
}

// ---------------- fallback streaming top-32 (exact, rare) --------------------
static __device__ __forceinline__ unsigned long long wmax64(unsigned long long m) {
    #pragma unroll
    for (int o = 16; o; o >>= 1) {
        unsigned long long ov = __shfl_xor_sync(FULLM, m, o);
        m = m > ov ? m : ov;
    }
    return m;
}

static __device__ __forceinline__ void winsert(unsigned long long c,
                                               unsigned long long& sc,
                                               unsigned long long& tau,
                                               int lane) {
    unsigned bal = __ballot_sync(FULLM, c < tau);
    while (bal) {
        int src = __ffs(bal) - 1;
        bal &= bal - 1;
        unsigned long long cn = __shfl_sync(FULLM, c, src);
        if (cn < tau) {
            unsigned eq = __ballot_sync(FULLM, sc == tau);
            if (lane == __ffs(eq) - 1) sc = cn;
            tau = wmax64(sc);
        }
    }
}

static __device__ __forceinline__ void wfinish(unsigned long long sc, int lane, int* out) {
    unsigned long long v1[1] = {sc};
    wsortu64<1>(v1, lane);
    if (lane < KK) out[lane] = (int)(v1[0] & 0xffffffffu);
}

// sort <=128 composites already in smem buf, emit KK indices
static __device__ __forceinline__ bool buf_finish(unsigned long long* bufw, int cnt,
                                                  int lane, int* out) {
    if (cnt > 128) return false;
    if (cnt <= 64) {
        unsigned long long e[2];
        e[0] = (lane < cnt) ? bufw[lane] : ULLMAX;
        e[1] = (lane + 32 < cnt) ? bufw[lane + 32] : ULLMAX;
        wsortu64<2>(e, lane);
        if (lane < KK) out[lane] = (int)(e[0] & 0xffffffffu);
    } else {
        unsigned long long e[4];
        #pragma unroll
        for (int rr = 0; rr < 4; rr++)
            e[rr] = (rr * 32 + lane < cnt) ? bufw[rr * 32 + lane] : ULLMAX;
        wsortu64<4>(e, lane);
        if (lane < KK) out[lane] = (int)(e[0] & 0xffffffffu);
    }
    return true;
}

// ---------------- fused init: pack x4, u0/v0, Wd1 ----------------------------
__global__ void init_k(const float* __restrict__ x,
                       const float* __restrict__ Wt0, const float* __restrict__ Wp0,
                       const float* __restrict__ Wt1, const float* __restrict__ Wp1) {
    int gid = blockIdx.x * 256 + threadIdx.x;   // NPTS*64 total
    int r = gid >> 6, c = gid & 63;
    float x0 = x[r * 3], x1 = x[r * 3 + 1], x2 = x[r * 3 + 2];
    float u = x0 * Wt0[c] + x1 * Wt0[64 + c] + x2 * Wt0[128 + c];
    float p = x0 * Wp0[c] + x1 * Wp0[64 + c] + x2 * Wp0[128 + c];
    g_u[gid] = u;
    g_v[gid] = p - u;
    if (gid < NPTS) {
        float a = x[gid * 3], b = x[gid * 3 + 1], cc = x[gid * 3 + 2];
        g_x4[gid] = make_float4(a, b, cc, a * a + b * b + cc * cc);
    }
    if (gid < 64 * 256) g_Wd1[gid] = Wp1[gid] - Wt1[gid];
}

// ---------------- fused 16-row (64->256) GEMM + h0 norms ---------------------
__global__ __launch_bounds__(256) void gemm16_k(const float* __restrict__ Wt1) {
    __shared__ float hs[16 * 64];
    int r0 = blockIdx.x * 16;
    int t = threadIdx.x;
    #pragma unroll
    for (int s = 0; s < 4; s++) {
        int l = t + (s << 8);
        hs[l] = g_h0[(size_t)r0 * 64 + l];
    }
    __syncthreads();
    // norms of these 16 rows (warp w handles rows 2w, 2w+1)
    {
        int w = t >> 5, lane = t & 31;
        #pragma unroll
        for (int rr = 0; rr < 2; rr++) {
            int r = w * 2 + rr;
            float a = hs[r * 64 + lane], b = hs[r * 64 + lane + 32];
            float s = a * a + b * b;
            #pragma unroll
            for (int o = 16; o; o >>= 1) s += __shfl_down_sync(FULLM, s, o);
            if (lane == 0) g_d2[r0 + r] = s;
        }
    }
    float au[16], av[16];
    #pragma unroll
    for (int r = 0; r < 16; r++) { au[r] = 0.f; av[r] = 0.f; }
    #pragma unroll 4
    for (int d = 0; d < 64; d++) {
        float wu = Wt1[d * 256 + t];
        float wv = g_Wd1[d * 256 + t];
        #pragma unroll
        for (int r = 0; r < 16; r++) {
            float h = hs[r * 64 + d];
            au[r] = fmaf(h, wu, au[r]);
            av[r] = fmaf(h, wv, av[r]);
        }
    }
    #pragma unroll
    for (int r = 0; r < 16; r++) {
        g_u[(size_t)(r0 + r) * 256 + t] = au[r];
        g_v[(size_t)(r0 + r) * 256 + t] = av[r];
    }
}

// ---------------- distance GEMM (layer1), triangular grid --------------------
static __device__ __forceinline__ int tri_start(int ti) {
    return ti * 64 - (ti * (ti - 1)) / 2;
}

__global__ __launch_bounds__(256) void dist_gemm_k() {
    const int b = blockIdx.y;
    int l = blockIdx.x;                    // 0..2079
    int ti = (int)((129.0f - sqrtf(129.0f * 129.0f - 8.0f * (float)l)) * 0.5f);
    if (ti > 63) ti = 63;
    while (ti < 63 && tri_start(ti + 1) <= l) ti++;
    while (ti > 0 && tri_start(ti) > l) ti--;
    int tj = ti + (l - tri_start(ti));
    const int i0 = ti * 64, j0 = tj * 64;
    __shared__ float As[64][65];
    __shared__ float Bs[64][65];
    const float* hb = g_h0 + (size_t)b * NN * 64;
    int t = threadIdx.x;
    #pragma unroll
    for (int s = 0; s < 16; s++) {
        int ll = t + (s << 8);
        int r = ll >> 6, d = ll & 63;
        As[d][r] = hb[(size_t)(i0 + r) * 64 + d];
        Bs[d][r] = hb[(size_t)(j0 + r) * 64 + d];
    }
    __syncthreads();
    int tx = t & 15, ty = t >> 4;
    float acc[4][4];
    #pragma unroll
    for (int r = 0; r < 4; r++)
        #pragma unroll
        for (int c = 0; c < 4; c++) acc[r][c] = 0.f;
    #pragma unroll 8
    for (int d = 0; d < 64; d++) {
        float a0 = As[d][ty * 4 + 0], a1 = As[d][ty * 4 + 1];
        float a2 = As[d][ty * 4 + 2], a3 = As[d][ty * 4 + 3];
        float b0 = Bs[d][tx * 4 + 0], b1 = Bs[d][tx * 4 + 1];
        float b2 = Bs[d][tx * 4 + 2], b3 = Bs[d][tx * 4 + 3];
        acc[0][0] = fmaf(a0, b0, acc[0][0]); acc[0][1] = fmaf(a0, b1, acc[0][1]);
        acc[0][2] = fmaf(a0, b2, acc[0][2]); acc[0][3] = fmaf(a0, b3, acc[0][3]);
        acc[1][0] = fmaf(a1, b0, acc[1][0]); acc[1][1] = fmaf(a1, b1, acc[1][1]);
        acc[1][2] = fmaf(a1, b2, acc[1][2]); acc[1][3] = fmaf(a1, b3, acc[1][3]);
        acc[2][0] = fmaf(a2, b0, acc[2][0]); acc[2][1] = fmaf(a2, b1, acc[2][1]);
        acc[2][2] = fmaf(a2, b2, acc[2][2]); acc[2][3] = fmaf(a2, b3, acc[2][3]);
        acc[3][0] = fmaf(a3, b0, acc[3][0]); acc[3][1] = fmaf(a3, b1, acc[3][1]);
        acc[3][2] = fmaf(a3, b2, acc[3][2]); acc[3][3] = fmaf(a3, b3, acc[3][3]);
    }
    const float* n2 = g_d2 + b * NN;
    float nj0 = n2[j0 + tx * 4 + 0], nj1 = n2[j0 + tx * 4 + 1];
    float nj2 = n2[j0 + tx * 4 + 2], nj3 = n2[j0 + tx * 4 + 3];
    float ov[4][4];
    #pragma unroll
    for (int r = 0; r < 4; r++) {
        float ni = n2[i0 + ty * 4 + r];
        ov[r][0] = ni + nj0 - 2.f * acc[r][0];
        ov[r][1] = ni + nj1 - 2.f * acc[r][1];
        ov[r][2] = ni + nj2 - 2.f * acc[r][2];
        ov[r][3] = ni + nj3 - 2.f * acc[r][3];
        *(float4*)&g_dist[((size_t)(b * NN + i0 + ty * 4 + r)) * NN + j0 + tx * 4] =
            make_float4(ov[r][0], ov[r][1], ov[r][2], ov[r][3]);
    }
    if (ti != tj) {
        __syncthreads();
        float* Ts = &As[0][0];                 // reuse [64][65]
        #pragma unroll
        for (int r = 0; r < 4; r++)
            #pragma unroll
            for (int c = 0; c < 4; c++)
                Ts[(tx * 4 + c) * 65 + (ty * 4 + r)] = ov[r][c];
        __syncthreads();
        #pragma unroll
        for (int s = 0; s < 16; s++) {
            int ll = t + (s << 8);
            int jr = ll >> 6, ic = ll & 63;
            g_dist[((size_t)(b * NN + j0 + jr)) * NN + i0 + ic] = Ts[jr * 65 + ic];
        }
    }
}

// ---------------- knn0: f32 pass1 + ballot-compact pass2 ---------------------
__global__ __launch_bounds__(256) void knn0_k() {
    __shared__ float4 pts[1024];                    // 16 KB
    __shared__ unsigned long long buf[8][128];      // 8 KB
    int t = threadIdx.x, w = t >> 5, lane = t & 31;
    int row = blockIdx.x * 8 + w;
    int base = row & ~(NN - 1);
    float4 me = g_x4[row];

    // pass 1: per-lane top-2 float distances (fma pipe)
    float m0 = FINF, m1 = FINF;
    #pragma unroll 1
    for (int chunk = 0; chunk < 4; chunk++) {
        __syncthreads();
        #pragma unroll
        for (int i = 0; i < 4; i++)
            pts[t + (i << 8)] = g_x4[base + (chunk << 10) + t + (i << 8)];
        __syncthreads();
        #pragma unroll 4
        for (int it = 0; it < 32; it++) {
            float4 p = pts[(it << 5) + lane];
            float dot = me.x * p.x + me.y * p.y + me.z * p.z;
            float d = me.w + p.w - 2.f * dot;
            if (d < m0) { m1 = m0; m0 = d; }
            else if (d < m1) { m1 = d; }
        }
    }
    float v2[2] = {m0, m1};
    wsortf<2>(v2, lane);
    float tau = __shfl_sync(FULLM, v2[0], 31);   // 32nd smallest collected

    // pass 2: ballot-compact composites of all d <= tau
    int cnt = 0;
    #pragma unroll 1
    for (int chunk = 0; chunk < 4; chunk++) {
        __syncthreads();
        #pragma unroll
        for (int i = 0; i < 4; i++)
            pts[t + (i << 8)] = g_x4[base + (chunk << 10) + t + (i << 8)];
        __syncthreads();
        #pragma unroll 4
        for (int it = 0; it < 32; it++) {
            int jl = (it << 5) + lane;
            float4 p = pts[jl];
            float dot = me.x * p.x + me.y * p.y + me.z * p.z;
            float d = me.w + p.w - 2.f * dot;
            unsigned mask = __ballot_sync(FULLM, d <= tau);
            if (d <= tau) {
                int pos = cnt + __popc(mask & ((1u << lane) - 1));
                if (pos < 128)
                    buf[w][pos] = ((unsigned long long)okey(d) << 32)
                                | (unsigned)((chunk << 10) + jl);
            }
            cnt += __popc(mask);
        }
    }
    int* out = g_idx + row * KK;
    if (!buf_finish(buf[w], cnt, lane, out)) {
        // exact streaming fallback (degenerate ties)
        unsigned long long sc, tau2;
        {
            float4 p = g_x4[base + lane];
            float dot = me.x * p.x + me.y * p.y + me.z * p.z;
            float d = me.w + p.w - 2.f * dot;
            sc = ((unsigned long long)okey(d) << 32) | (unsigned)lane;
            tau2 = wmax64(sc);
        }
        for (int it = 1; it < 128; it++) {
            int j = (it << 5) + lane;
            float4 p = g_x4[base + j];
            float dot = me.x * p.x + me.y * p.y + me.z * p.z;
            float d = me.w + p.w - 2.f * dot;
            unsigned long long c = ((unsigned long long)okey(d) << 32) | (unsigned)j;
            winsert(c, sc, tau2, lane);
        }
        wfinish(sc, lane, out);
    }
}

// ---------------- knn1: f32 pass1 + ballot-compact pass2 over dist rows ------
__global__ __launch_bounds__(256) void knn1_k() {
    __shared__ unsigned long long buf[8][128];      // 8 KB
    int t = threadIdx.x, w = t >> 5, lane = t & 31;
    int row = blockIdx.x * 8 + w;
    const float4* dr = (const float4*)(g_dist + (size_t)row * NN);   // 1024 float4

    // pass 1
    float m0 = FINF, m1 = FINF;
    #pragma unroll 4
    for (int it = 0; it < 32; it++) {
        float4 dv = __ldg(&dr[(it << 5) + lane]);
        if (dv.x < m0) { m1 = m0; m0 = dv.x; } else if (dv.x < m1) m1 = dv.x;
        if (dv.y < m0) { m1 = m0; m0 = dv.y; } else if (dv.y < m1) m1 = dv.y;
        if (dv.z < m0) { m1 = m0; m0 = dv.z; } else if (dv.z < m1) m1 = dv.z;
        if (dv.w < m0) { m1 = m0; m0 = dv.w; } else if (dv.w < m1) m1 = dv.w;
    }
    float v2[2] = {m0, m1};
    wsortf<2>(v2, lane);
    float tau = __shfl_sync(FULLM, v2[0], 31);

    // pass 2 (row L1-resident)
    int cnt = 0;
    #pragma unroll 2
    for (int it = 0; it < 32; it++) {
        int j4 = (it << 5) + lane;
        float4 dv = __ldg(&dr[j4]);
        int jb = j4 << 2;
        float ds[4] = {dv.x, dv.y, dv.z, dv.w};
        #pragma unroll
        for (int q = 0; q < 4; q++) {
            float d = ds[q];
            unsigned mask = __ballot_sync(FULLM, d <= tau);
            if (d <= tau) {
                int pos = cnt + __popc(mask & ((1u << lane) - 1));
                if (pos < 128)
                    buf[w][pos] = ((unsigned long long)okey(d) << 32) | (unsigned)(jb + q);
            }
            cnt += __popc(mask);
        }
    }
    int* out = g_idx + row * KK;
    if (!buf_finish(buf[w], cnt, lane, out)) {
        const float* drs = g_dist + (size_t)row * NN;
        unsigned long long sc, tau2;
        {
            sc = ((unsigned long long)okey(drs[lane]) << 32) | (unsigned)lane;
            tau2 = wmax64(sc);
        }
        for (int it = 1; it < 128; it++) {
            int j = (it << 5) + lane;
            unsigned long long c = ((unsigned long long)okey(__ldg(&drs[j])) << 32) | (unsigned)j;
            winsert(c, sc, tau2, lane);
        }
        wfinish(sc, lane, out);
    }
}

// ---------------- fused gather: BN stats + per-point neighbor vmax/vmin ------
template <int C>
__global__ __launch_bounds__(256) void gather_k() {
    constexpr int G = 256 / C;
    int t = threadIdx.x;
    int c = t % C;
    int g = t / C;
    float s = 0.f, s2 = 0.f;
    for (int p = blockIdx.x * G + g; p < NPTS; p += STATS_BLOCKS * G) {
        int b = p >> 12;
        float uc = g_u[(size_t)p * C + c];
        const int* ip = g_idx + p * KK;
        float S = 0.f, Q = 0.f, mx = -FINF, mn = FINF;
        #pragma unroll
        for (int k = 0; k < KK; k++) {
            int j = ip[k];
            float v = g_v[((size_t)((b << 12) + j)) * C + c];
            S += v;
            Q = fmaf(v, v, Q);
            mx = fmaxf(mx, v);
            mn = fminf(mn, v);
        }
        g_vmax[(size_t)p * C + c] = mx;
        g_vmin[(size_t)p * C + c] = mn;
        s += fmaf(20.f, uc, S);
        s2 += fmaf(20.f * uc, uc, fmaf(2.f * uc, S, Q));
    }
    __shared__ float sh[256], sh2[256];
    sh[t] = s; sh2[t] = s2;
    __syncthreads();
    if (t < C) {
        float S = sh[t], S2 = sh2[t];
        #pragma unroll
        for (int gg = 1; gg < G; gg++) { S += sh[gg * C + t]; S2 += sh2[gg * C + t]; }
        g_part[blockIdx.x * (2 * C) + t] = S;
        g_part[blockIdx.x * (2 * C) + C + t] = S2;
    }
}

template <int C>
__global__ void fin_k(const float* __restrict__ gamma, const float* __restrict__ beta) {
    int c = threadIdx.x;
    float S = 0.f, S2 = 0.f;
    for (int bk = 0; bk < STATS_BLOCKS; bk++) {
        S += g_part[bk * 2 * C + c];
        S2 += g_part[bk * 2 * C + C + c];
    }
    const float inv = 1.f / (float)EDG;
    float mu = S * inv;
    float var = S2 * inv - mu * mu;
    float sc = gamma[c] * rsqrtf(var + 1e-5f);
    g_scale[c] = sc;
    g_shift[c] = beta[c] - mu * sc;
}

// ---------------- finish layer0: h0 = leaky(...) ------------------------------
__global__ void finish64_k() {
    int gid = blockIdx.x * 256 + threadIdx.x;    // NPTS*64
    int c = gid & 63;
    float sc = g_scale[c];
    float vm = (sc >= 0.f) ? g_vmax[gid] : g_vmin[gid];
    float M = g_u[gid] + vm;
    g_h0[gid] = leaky(fmaf(M, sc, g_shift[c]));
}

// ---------------- finish layer1 + fused attention gate -----------------------
__global__ __launch_bounds__(256) void finish256_k(const float* __restrict__ Wg,
                                                   const float* __restrict__ bg) {
    __shared__ float sh[256];
    int p = blockIdx.x;                           // one point per block
    int c = threadIdx.x;
    size_t gid = (size_t)p * 256 + c;
    float sc = g_scale[c];
    float vm = (sc >= 0.f) ? g_vmax[gid] : g_vmin[gid];
    float h = leaky(fmaf(g_u[gid] + vm, sc, g_shift[c]));
    g_h1[gid] = h;
    sh[c] = h * Wg[c];
    __syncthreads();
    #pragma unroll
    for (int o = 128; o; o >>= 1) {
        if (c < o) sh[c] += sh[c + o];
        __syncthreads();
    }
    if (c == 0) {
        float gg = sh[0] + bg[0];
        g_gate[p] = gg > 0.f ? gg : 0.f;
    }
}

__global__ void softmax_k() {
    int b = blockIdx.x, t = threadIdx.x;
    __shared__ float sh[256];
    const float* gp = g_gate + (b << 12);
    float* ap = g_alpha + (b << 12);
    float mx = -FINF;
    for (int s = 0; s < 16; s++) mx = fmaxf(mx, gp[t + (s << 8)]);
    sh[t] = mx; __syncthreads();
    for (int o = 128; o; o >>= 1) { if (t < o) sh[t] = fmaxf(sh[t], sh[t + o]); __syncthreads(); }
    float M = sh[0];
    __syncthreads();
    float sum = 0.f;
    for (int s = 0; s < 16; s++) {
        int j = t + (s << 8);
        float e = expf(gp[j] - M);
        ap[j] = e;
        sum += e;
    }
    sh[t] = sum; __syncthreads();
    for (int o = 128; o; o >>= 1) { if (t < o) sh[t] += sh[t + o]; __syncthreads(); }
    float inv = 1.f / sh[0];
    for (int s = 0; s < 16; s++) ap[t + (s << 8)] *= inv;
}

// ---------------- fused feat GEMM + weighted pooling --------------------------
__global__ __launch_bounds__(256) void pool_k(const float* __restrict__ Wf,
                                              const float* __restrict__ bf) {
    int b = blockIdx.x;
    int t = threadIdx.x;
    int ch = blockIdx.y * 256 + t;
    int slab = blockIdx.z;
    __shared__ float hr[16][256];
    __shared__ float al[16];
    float acc = 0.f;
    float bfc = bf[ch];
    for (int gidx = 0; gidx < 8; gidx++) {
        int nb = (slab << 7) + (gidx << 4);
        __syncthreads();
        #pragma unroll
        for (int s = 0; s < 16; s++)
            hr[s][t] = g_h1[((size_t)(b << 12) + nb + s) * 256 + t];
        if (t < 16) al[t] = g_alpha[(b << 12) + nb + t];
        __syncthreads();
        float sacc[16];
        #pragma unroll
        for (int r = 0; r < 16; r++) sacc[r] = bfc;
        #pragma unroll 4
        for (int d = 0; d < 256; d += 4) {
            float w0 = Wf[(d + 0) * 512 + ch];
            float w1 = Wf[(d + 1) * 512 + ch];
            float w2 = Wf[(d + 2) * 512 + ch];
            float w3 = Wf[(d + 3) * 512 + ch];
            #pragma unroll
            for (int r = 0; r < 16; r++) {
                float4 hv = *(const float4*)&hr[r][d];
                sacc[r] = fmaf(hv.x, w0, fmaf(hv.y, w1, fmaf(hv.z, w2, fmaf(hv.w, w3, sacc[r]))));
            }
        }
        #pragma unroll
        for (int r = 0; r < 16; r++) {
            float f = sacc[r] > 0.f ? sacc[r] : 0.f;
            acc = fmaf(al[r], f, acc);
        }
    }
    g_pool[((slab << 2) + b) * 512 + ch] = acc;
}

__global__ void poolred_k() {
    int gid = blockIdx.x * 256 + threadIdx.x;  // BB*512
    if (gid >= BB * 512) return;
    int b = gid >> 9, ch = gid & 511;
    float s = 0.f;
    for (int sl = 0; sl < 32; sl++) s += g_pool[((sl << 2) + b) * 512 + ch];
    g_pooled[gid] = s;
}

__global__ void final_k(const float* __restrict__ Wl, const float* __restrict__ bl,
                        float* __restrict__ out) {
    int b = blockIdx.x, o = threadIdx.x;
    const float* p = g_pooled + b * 512;
    float s = bl[o];
    #pragma unroll 8
    for (int f = 0; f < 512; f++) s = fmaf(p[f], Wl[f * 256 + o], s);
    out[b * 256 + o] = s;
}

// ---------------- launch ------------------------------------------------------
extern "C" void kernel_launch(void* const* d_in, const int* in_sizes, int n_in,
                              void* d_out, int out_size) {
    (void)in_sizes; (void)n_in; (void)out_size;
    const float* x   = (const float*)d_in[0];
    const float* Wt0 = (const float*)d_in[1];
    const float* Wp0 = (const float*)d_in[3];
    const float* g0  = (const float*)d_in[5];
    const float* be0 = (const float*)d_in[6];
    const float* Wt1 = (const float*)d_in[7];
    const float* Wp1 = (const float*)d_in[9];
    const float* g1  = (const float*)d_in[11];
    const float* be1 = (const float*)d_in[12];
    const float* Wg  = (const float*)d_in[13];
    const float* bg  = (const float*)d_in[14];
    const float* Wf  = (const float*)d_in[15];
    const float* bf  = (const float*)d_in[16];
    const float* Wl  = (const float*)d_in[17];
    const float* bl  = (const float*)d_in[18];
    float* out = (float*)d_out;

    // ---- layer 0 ----
    init_k<<<NPTS * 64 / 256, 256>>>(x, Wt0, Wp0, Wt1, Wp1);
    knn0_k<<<NPTS / 8, 256>>>();
    gather_k<64><<<STATS_BLOCKS, 256>>>();
    fin_k<64><<<1, 64>>>(g0, be0);
    finish64_k<<<NPTS * 64 / 256, 256>>>();

    // ---- layer 1 ----
    gemm16_k<<<NPTS / 16, 256>>>(Wt1);               // u1, v1, norms fused
    dist_gemm_k<<<dim3(2080, BB), 256>>>();
    knn1_k<<<NPTS / 8, 256>>>();
    gather_k<256><<<STATS_BLOCKS, 256>>>();
    fin_k<256><<<1, 256>>>(g1, be1);
    finish256_k<<<NPTS, 256>>>(Wg, bg);              // h1 + gate fused

    // ---- attention pooling + final linear ----
    softmax_k<<<BB, 256>>>();
    pool_k<<<dim3(BB, 2, 32), 256>>>(Wf, bf);
    poolred_k<<<8, 256>>>();
    final_k<<<BB, 256>>>(Wl, bl, out);
}

// round 14
// speedup vs baseline: 1.0685x; 1.0473x over previous
#include <cuda_runtime.h>
#include <math.h>

#define BB 4
#define NN 4096
#define KK 20
#define NPTS (BB*NN)            // 16384
#define EDG  (NPTS*KK)          // 327680
#define STATS_BLOCKS 512
#define FULLM 0xffffffffu

#define FINF __int_as_float(0x7f800000)
#define ULLMAX 0xFFFFFFFFFFFFFFFFULL

// ---------------- scratch (device globals; no allocations allowed) ----------
__device__ float g_dist[(size_t)BB * NN * NN];      // float distances (layer 1)
__device__ float4 g_x4[NPTS];                        // packed (x,y,z,|x|^2)
__device__ float g_d2[NPTS];
__device__ int   g_idx[NPTS * KK];
__device__ float g_u[NPTS * 256];
__device__ float g_v[NPTS * 256];
__device__ float g_vmax[NPTS * 256];
__device__ float g_vmin[NPTS * 256];
__device__ float g_h0[NPTS * 64];
__device__ float g_h1[NPTS * 256];
__device__ float g_Wd1[64 * 256];
__device__ float g_part[STATS_BLOCKS * 2 * 256];
__device__ float g_scale[256];
__device__ float g_shift[256];
__device__ float g_gate[NPTS];
__device__ float g_alpha[NPTS];
__device__ float g_pool[32 * BB * 512];
__device__ float g_pooled[BB * 512];

static __device__ __forceinline__ float leaky(float v) { return v > 0.f ? v : 0.2f * v; }

// float -> order-preserving uint (ascending float == ascending uint)
static __device__ __forceinline__ unsigned okey(float f) {
    unsigned u = __float_as_uint(f);
    return u ^ ((unsigned)(((int)u) >> 31) | 0x80000000u);
}

// ---------------- warp bitonic sorts ------------------------------------------
template <int NR>
static __device__ __forceinline__ void wsortf(float* v, int lane) {
    const int N = NR * 32;
    #pragma unroll
    for (int k = 2; k <= N; k <<= 1) {
        #pragma unroll
        for (int j = k >> 1; j > 0; j >>= 1) {
            if (j >= 32) {
                int rj = j >> 5;
                #pragma unroll
                for (int rr = 0; rr < NR; rr++) {
                    int pr = rr ^ rj;
                    if (pr > rr) {
                        int p = rr * 32 + lane;
                        bool asc = ((p & k) == 0);
                        float a = v[rr], b = v[pr];
                        float mn = fminf(a, b), mx = fmaxf(a, b);
                        v[rr] = asc ? mn : mx;
                        v[pr] = asc ? mx : mn;
                    }
                }
            } else {
                #pragma unroll
                for (int rr = 0; rr < NR; rr++) {
                    int p = rr * 32 + lane;
                    bool asc = ((p & k) == 0);
                    bool lower = ((lane & j) == 0);
                    float o = __shfl_xor_sync(FULLM, v[rr], j);
                    bool keepmin = (asc == lower);
                    float mn = fminf(v[rr], o), mx = fmaxf(v[rr], o);
                    v[rr] = keepmin ? mn : mx;
                }
            }
        }
    }
}

template <int NR>
static __device__ __forceinline__ void wsortu64(unsigned long long* v, int lane) {
    const int N = NR * 32;
    #pragma unroll
    for (int k = 2; k <= N; k <<= 1) {
        #pragma unroll
        for (int j = k >> 1; j > 0; j >>= 1) {
            if (j >= 32) {
                int rj = j >> 5;
                #pragma unroll
                for (int rr = 0; rr < NR; rr++) {
                    int pr = rr ^ rj;
                    if (pr > rr) {
                        int p = rr * 32 + lane;
                        bool asc = ((p & k) == 0);
                        unsigned long long a = v[rr], b = v[pr];
                        unsigned long long mn = a < b ? a : b;
                        unsigned long long mx = a < b ? b : a;
                        v[rr] = asc ? mn : mx;
                        v[pr] = asc ? mx : mn;
                    }
                }
            } else {
                #pragma unroll
                for (int rr = 0; rr < NR; rr++) {
                    int p = rr * 32 + lane;
                    bool asc = ((p & k) == 0);
                    bool lower = ((lane & j) == 0);
                    unsigned long long o = __shfl_xor_sync(FULLM, v[rr], j);
                    bool keepmin = (asc == lower);
                    unsigned long long mn = v[rr] < o ? v[rr] : o;
                    unsigned long long mx = v[rr] < o ? o : v[rr];
                    v[rr] = keepmin ? mn : mx;
                }
            }
        }
    }
}

// ---------------- fallback streaming top-32 (exact, rare) --------------------
static __device__ __forceinline__ unsigned long long wmax64(unsigned long long m) {
    #pragma unroll
    for (int o = 16; o; o >>= 1) {
        unsigned long long ov = __shfl_xor_sync(FULLM, m, o);
        m = m > ov ? m : ov;
    }
    return m;
}

static __device__ __forceinline__ void winsert(unsigned long long c,
                                               unsigned long long& sc,
                                               unsigned long long& tau,
                                               int lane) {
    unsigned bal = __ballot_sync(FULLM, c < tau);
    while (bal) {
        int src = __ffs(bal) - 1;
        bal &= bal - 1;
        unsigned long long cn = __shfl_sync(FULLM, c, src);
        if (cn < tau) {
            unsigned eq = __ballot_sync(FULLM, sc == tau);
            if (lane == __ffs(eq) - 1) sc = cn;
            tau = wmax64(sc);
        }
    }
}

static __device__ __forceinline__ void wfinish(unsigned long long sc, int lane, int* out) {
    unsigned long long v1[1] = {sc};
    wsortu64<1>(v1, lane);
    if (lane < KK) out[lane] = (int)(v1[0] & 0xffffffffu);
}

// sort <=128 composites already in smem buf, emit KK indices
static __device__ __forceinline__ bool buf_finish(unsigned long long* bufw, int cnt,
                                                  int lane, int* out) {
    if (cnt > 128) return false;
    if (cnt <= 64) {
        unsigned long long e[2];
        e[0] = (lane < cnt) ? bufw[lane] : ULLMAX;
        e[1] = (lane + 32 < cnt) ? bufw[lane + 32] : ULLMAX;
        wsortu64<2>(e, lane);
        if (lane < KK) out[lane] = (int)(e[0] & 0xffffffffu);
    } else {
        unsigned long long e[4];
        #pragma unroll
        for (int rr = 0; rr < 4; rr++)
            e[rr] = (rr * 32 + lane < cnt) ? bufw[rr * 32 + lane] : ULLMAX;
        wsortu64<4>(e, lane);
        if (lane < KK) out[lane] = (int)(e[0] & 0xffffffffu);
    }
    return true;
}

// ---------------- fused init: pack x4, u0/v0, Wd1 ----------------------------
__global__ void init_k(const float* __restrict__ x,
                       const float* __restrict__ Wt0, const float* __restrict__ Wp0,
                       const float* __restrict__ Wt1, const float* __restrict__ Wp1) {
    int gid = blockIdx.x * 256 + threadIdx.x;   // NPTS*64 total
    int r = gid >> 6, c = gid & 63;
    float x0 = x[r * 3], x1 = x[r * 3 + 1], x2 = x[r * 3 + 2];
    float u = x0 * Wt0[c] + x1 * Wt0[64 + c] + x2 * Wt0[128 + c];
    float p = x0 * Wp0[c] + x1 * Wp0[64 + c] + x2 * Wp0[128 + c];
    g_u[gid] = u;
    g_v[gid] = p - u;
    if (gid < NPTS) {
        float a = x[gid * 3], b = x[gid * 3 + 1], cc = x[gid * 3 + 2];
        g_x4[gid] = make_float4(a, b, cc, a * a + b * b + cc * cc);
    }
    if (gid < 64 * 256) g_Wd1[gid] = Wp1[gid] - Wt1[gid];
}

// ---------------- fused 16-row (64->256) GEMM + h0 norms ---------------------
__global__ __launch_bounds__(256) void gemm16_k(const float* __restrict__ Wt1) {
    __shared__ float hs[16 * 64];
    int r0 = blockIdx.x * 16;
    int t = threadIdx.x;
    #pragma unroll
    for (int s = 0; s < 4; s++) {
        int l = t + (s << 8);
        hs[l] = g_h0[(size_t)r0 * 64 + l];
    }
    __syncthreads();
    // norms of these 16 rows (warp w handles rows 2w, 2w+1)
    {
        int w = t >> 5, lane = t & 31;
        #pragma unroll
        for (int rr = 0; rr < 2; rr++) {
            int r = w * 2 + rr;
            float a = hs[r * 64 + lane], b = hs[r * 64 + lane + 32];
            float s = a * a + b * b;
            #pragma unroll
            for (int o = 16; o; o >>= 1) s += __shfl_down_sync(FULLM, s, o);
            if (lane == 0) g_d2[r0 + r] = s;
        }
    }
    float au[16], av[16];
    #pragma unroll
    for (int r = 0; r < 16; r++) { au[r] = 0.f; av[r] = 0.f; }
    #pragma unroll 4
    for (int d = 0; d < 64; d++) {
        float wu = Wt1[d * 256 + t];
        float wv = g_Wd1[d * 256 + t];
        #pragma unroll
        for (int r = 0; r < 16; r++) {
            float h = hs[r * 64 + d];
            au[r] = fmaf(h, wu, au[r]);
            av[r] = fmaf(h, wv, av[r]);
        }
    }
    #pragma unroll
    for (int r = 0; r < 16; r++) {
        g_u[(size_t)(r0 + r) * 256 + t] = au[r];
        g_v[(size_t)(r0 + r) * 256 + t] = av[r];
    }
}

// ---------------- distance GEMM (layer1), triangular grid --------------------
static __device__ __forceinline__ int tri_start(int ti) {
    return ti * 64 - (ti * (ti - 1)) / 2;
}

__global__ __launch_bounds__(256) void dist_gemm_k() {
    const int b = blockIdx.y;
    int l = blockIdx.x;                    // 0..2079
    int ti = (int)((129.0f - sqrtf(129.0f * 129.0f - 8.0f * (float)l)) * 0.5f);
    if (ti > 63) ti = 63;
    while (ti < 63 && tri_start(ti + 1) <= l) ti++;
    while (ti > 0 && tri_start(ti) > l) ti--;
    int tj = ti + (l - tri_start(ti));
    const int i0 = ti * 64, j0 = tj * 64;
    __shared__ float As[64][65];
    __shared__ float Bs[64][65];
    const float* hb = g_h0 + (size_t)b * NN * 64;
    int t = threadIdx.x;
    #pragma unroll
    for (int s = 0; s < 16; s++) {
        int ll = t + (s << 8);
        int r = ll >> 6, d = ll & 63;
        As[d][r] = hb[(size_t)(i0 + r) * 64 + d];
        Bs[d][r] = hb[(size_t)(j0 + r) * 64 + d];
    }
    __syncthreads();
    int tx = t & 15, ty = t >> 4;
    float acc[4][4];
    #pragma unroll
    for (int r = 0; r < 4; r++)
        #pragma unroll
        for (int c = 0; c < 4; c++) acc[r][c] = 0.f;
    #pragma unroll 8
    for (int d = 0; d < 64; d++) {
        float a0 = As[d][ty * 4 + 0], a1 = As[d][ty * 4 + 1];
        float a2 = As[d][ty * 4 + 2], a3 = As[d][ty * 4 + 3];
        float b0 = Bs[d][tx * 4 + 0], b1 = Bs[d][tx * 4 + 1];
        float b2 = Bs[d][tx * 4 + 2], b3 = Bs[d][tx * 4 + 3];
        acc[0][0] = fmaf(a0, b0, acc[0][0]); acc[0][1] = fmaf(a0, b1, acc[0][1]);
        acc[0][2] = fmaf(a0, b2, acc[0][2]); acc[0][3] = fmaf(a0, b3, acc[0][3]);
        acc[1][0] = fmaf(a1, b0, acc[1][0]); acc[1][1] = fmaf(a1, b1, acc[1][1]);
        acc[1][2] = fmaf(a1, b2, acc[1][2]); acc[1][3] = fmaf(a1, b3, acc[1][3]);
        acc[2][0] = fmaf(a2, b0, acc[2][0]); acc[2][1] = fmaf(a2, b1, acc[2][1]);
        acc[2][2] = fmaf(a2, b2, acc[2][2]); acc[2][3] = fmaf(a2, b3, acc[2][3]);
        acc[3][0] = fmaf(a3, b0, acc[3][0]); acc[3][1] = fmaf(a3, b1, acc[3][1]);
        acc[3][2] = fmaf(a3, b2, acc[3][2]); acc[3][3] = fmaf(a3, b3, acc[3][3]);
    }
    const float* n2 = g_d2 + b * NN;
    float nj0 = n2[j0 + tx * 4 + 0], nj1 = n2[j0 + tx * 4 + 1];
    float nj2 = n2[j0 + tx * 4 + 2], nj3 = n2[j0 + tx * 4 + 3];
    float ov[4][4];
    #pragma unroll
    for (int r = 0; r < 4; r++) {
        float ni = n2[i0 + ty * 4 + r];
        ov[r][0] = ni + nj0 - 2.f * acc[r][0];
        ov[r][1] = ni + nj1 - 2.f * acc[r][1];
        ov[r][2] = ni + nj2 - 2.f * acc[r][2];
        ov[r][3] = ni + nj3 - 2.f * acc[r][3];
        *(float4*)&g_dist[((size_t)(b * NN + i0 + ty * 4 + r)) * NN + j0 + tx * 4] =
            make_float4(ov[r][0], ov[r][1], ov[r][2], ov[r][3]);
    }
    if (ti != tj) {
        __syncthreads();
        float* Ts = &As[0][0];                 // reuse [64][65]
        #pragma unroll
        for (int r = 0; r < 4; r++)
            #pragma unroll
            for (int c = 0; c < 4; c++)
                Ts[(tx * 4 + c) * 65 + (ty * 4 + r)] = ov[r][c];
        __syncthreads();
        #pragma unroll
        for (int s = 0; s < 16; s++) {
            int ll = t + (s << 8);
            int jr = ll >> 6, ic = ll & 63;
            g_dist[((size_t)(b * NN + j0 + jr)) * NN + i0 + ic] = Ts[jr * 65 + ic];
        }
    }
}

// ---------------- knn0: f32 pass1 + ballot-compact pass2 ---------------------
__global__ __launch_bounds__(256) void knn0_k() {
    __shared__ float4 pts[1024];                    // 16 KB
    __shared__ unsigned long long buf[8][128];      // 8 KB
    int t = threadIdx.x, w = t >> 5, lane = t & 31;
    int row = blockIdx.x * 8 + w;
    int base = row & ~(NN - 1);
    float4 me = g_x4[row];

    // pass 1: per-lane top-2 float distances (fma pipe)
    float m0 = FINF, m1 = FINF;
    #pragma unroll 1
    for (int chunk = 0; chunk < 4; chunk++) {
        __syncthreads();
        #pragma unroll
        for (int i = 0; i < 4; i++)
            pts[t + (i << 8)] = g_x4[base + (chunk << 10) + t + (i << 8)];
        __syncthreads();
        #pragma unroll 4
        for (int it = 0; it < 32; it++) {
            float4 p = pts[(it << 5) + lane];
            float dot = me.x * p.x + me.y * p.y + me.z * p.z;
            float d = me.w + p.w - 2.f * dot;
            if (d < m0) { m1 = m0; m0 = d; }
            else if (d < m1) { m1 = d; }
        }
    }
    float v2[2] = {m0, m1};
    wsortf<2>(v2, lane);
    float tau = __shfl_sync(FULLM, v2[0], 31);   // 32nd smallest collected

    // pass 2: ballot-compact composites of all d <= tau
    int cnt = 0;
    #pragma unroll 1
    for (int chunk = 0; chunk < 4; chunk++) {
        __syncthreads();
        #pragma unroll
        for (int i = 0; i < 4; i++)
            pts[t + (i << 8)] = g_x4[base + (chunk << 10) + t + (i << 8)];
        __syncthreads();
        #pragma unroll 4
        for (int it = 0; it < 32; it++) {
            int jl = (it << 5) + lane;
            float4 p = pts[jl];
            float dot = me.x * p.x + me.y * p.y + me.z * p.z;
            float d = me.w + p.w - 2.f * dot;
            unsigned mask = __ballot_sync(FULLM, d <= tau);
            if (d <= tau) {
                int pos = cnt + __popc(mask & ((1u << lane) - 1));
                if (pos < 128)
                    buf[w][pos] = ((unsigned long long)okey(d) << 32)
                                | (unsigned)((chunk << 10) + jl);
            }
            cnt += __popc(mask);
        }
    }
    int* out = g_idx + row * KK;
    if (!buf_finish(buf[w], cnt, lane, out)) {
        // exact streaming fallback (degenerate ties)
        unsigned long long sc, tau2;
        {
            float4 p = g_x4[base + lane];
            float dot = me.x * p.x + me.y * p.y + me.z * p.z;
            float d = me.w + p.w - 2.f * dot;
            sc = ((unsigned long long)okey(d) << 32) | (unsigned)lane;
            tau2 = wmax64(sc);
        }
        for (int it = 1; it < 128; it++) {
            int j = (it << 5) + lane;
            float4 p = g_x4[base + j];
            float dot = me.x * p.x + me.y * p.y + me.z * p.z;
            float d = me.w + p.w - 2.f * dot;
            unsigned long long c = ((unsigned long long)okey(d) << 32) | (unsigned)j;
            winsert(c, sc, tau2, lane);
        }
        wfinish(sc, lane, out);
    }
}

// ---------------- knn1: f32 pass1 + ballot-compact pass2 over dist rows ------
__global__ __launch_bounds__(256) void knn1_k() {
    __shared__ unsigned long long buf[8][128];      // 8 KB
    int t = threadIdx.x, w = t >> 5, lane = t & 31;
    int row = blockIdx.x * 8 + w;
    const float4* dr = (const float4*)(g_dist + (size_t)row * NN);   // 1024 float4

    // pass 1
    float m0 = FINF, m1 = FINF;
    #pragma unroll 4
    for (int it = 0; it < 32; it++) {
        float4 dv = __ldg(&dr[(it << 5) + lane]);
        if (dv.x < m0) { m1 = m0; m0 = dv.x; } else if (dv.x < m1) m1 = dv.x;
        if (dv.y < m0) { m1 = m0; m0 = dv.y; } else if (dv.y < m1) m1 = dv.y;
        if (dv.z < m0) { m1 = m0; m0 = dv.z; } else if (dv.z < m1) m1 = dv.z;
        if (dv.w < m0) { m1 = m0; m0 = dv.w; } else if (dv.w < m1) m1 = dv.w;
    }
    float v2[2] = {m0, m1};
    wsortf<2>(v2, lane);
    float tau = __shfl_sync(FULLM, v2[0], 31);

    // pass 2 (row L1-resident)
    int cnt = 0;
    #pragma unroll 2
    for (int it = 0; it < 32; it++) {
        int j4 = (it << 5) + lane;
        float4 dv = __ldg(&dr[j4]);
        int jb = j4 << 2;
        float ds[4] = {dv.x, dv.y, dv.z, dv.w};
        #pragma unroll
        for (int q = 0; q < 4; q++) {
            float d = ds[q];
            unsigned mask = __ballot_sync(FULLM, d <= tau);
            if (d <= tau) {
                int pos = cnt + __popc(mask & ((1u << lane) - 1));
                if (pos < 128)
                    buf[w][pos] = ((unsigned long long)okey(d) << 32) | (unsigned)(jb + q);
            }
            cnt += __popc(mask);
        }
    }
    int* out = g_idx + row * KK;
    if (!buf_finish(buf[w], cnt, lane, out)) {
        const float* drs = g_dist + (size_t)row * NN;
        unsigned long long sc, tau2;
        {
            sc = ((unsigned long long)okey(drs[lane]) << 32) | (unsigned)lane;
            tau2 = wmax64(sc);
        }
        for (int it = 1; it < 128; it++) {
            int j = (it << 5) + lane;
            unsigned long long c = ((unsigned long long)okey(__ldg(&drs[j])) << 32) | (unsigned)j;
            winsert(c, sc, tau2, lane);
        }
        wfinish(sc, lane, out);
    }
}

// ---------------- fused gather: BN stats + per-point neighbor vmax/vmin ------
template <int C>
__global__ __launch_bounds__(256) void gather_k() {
    constexpr int G = 256 / C;
    int t = threadIdx.x;
    int c = t % C;
    int g = t / C;
    float s = 0.f, s2 = 0.f;
    for (int p = blockIdx.x * G + g; p < NPTS; p += STATS_BLOCKS * G) {
        int b = p >> 12;
        float uc = g_u[(size_t)p * C + c];
        const int* ip = g_idx + p * KK;
        float S = 0.f, Q = 0.f, mx = -FINF, mn = FINF;
        #pragma unroll
        for (int k = 0; k < KK; k++) {
            int j = ip[k];
            float v = g_v[((size_t)((b << 12) + j)) * C + c];
            S += v;
            Q = fmaf(v, v, Q);
            mx = fmaxf(mx, v);
            mn = fminf(mn, v);
        }
        g_vmax[(size_t)p * C + c] = mx;
        g_vmin[(size_t)p * C + c] = mn;
        s += fmaf(20.f, uc, S);
        s2 += fmaf(20.f * uc, uc, fmaf(2.f * uc, S, Q));
    }
    __shared__ float sh[256], sh2[256];
    sh[t] = s; sh2[t] = s2;
    __syncthreads();
    if (t < C) {
        float S = sh[t], S2 = sh2[t];
        #pragma unroll
        for (int gg = 1; gg < G; gg++) { S += sh[gg * C + t]; S2 += sh2[gg * C + t]; }
        g_part[blockIdx.x * (2 * C) + t] = S;
        g_part[blockIdx.x * (2 * C) + C + t] = S2;
    }
}

// ---------------- finalize BN scale/shift: one block per channel -------------
template <int C>
__global__ __launch_bounds__(256) void fin_k(const float* __restrict__ gamma,
                                             const float* __restrict__ beta) {
    int c = blockIdx.x;          // channel
    int t = threadIdx.x;
    float S = 0.f, S2 = 0.f;
    #pragma unroll
    for (int bk = t; bk < STATS_BLOCKS; bk += 256) {
        S += g_part[bk * 2 * C + c];
        S2 += g_part[bk * 2 * C + C + c];
    }
    #pragma unroll
    for (int o = 16; o; o >>= 1) {
        S += __shfl_down_sync(FULLM, S, o);
        S2 += __shfl_down_sync(FULLM, S2, o);
    }
    __shared__ float sh[8], sh2[8];
    int w = t >> 5, lane = t & 31;
    if (lane == 0) { sh[w] = S; sh2[w] = S2; }
    __syncthreads();
    if (t == 0) {
        float Sa = 0.f, S2a = 0.f;
        #pragma unroll
        for (int i = 0; i < 8; i++) { Sa += sh[i]; S2a += sh2[i]; }
        const float inv = 1.f / (float)EDG;
        float mu = Sa * inv;
        float var = S2a * inv - mu * mu;
        float sc = gamma[c] * rsqrtf(var + 1e-5f);
        g_scale[c] = sc;
        g_shift[c] = beta[c] - mu * sc;
    }
}

// ---------------- finish layer0: h0 = leaky(...) ------------------------------
__global__ void finish64_k() {
    int gid = blockIdx.x * 256 + threadIdx.x;    // NPTS*64
    int c = gid & 63;
    float sc = g_scale[c];
    float vm = (sc >= 0.f) ? g_vmax[gid] : g_vmin[gid];
    float M = g_u[gid] + vm;
    g_h0[gid] = leaky(fmaf(M, sc, g_shift[c]));
}

// ---------------- finish layer1 + fused attention gate -----------------------
__global__ __launch_bounds__(256) void finish256_k(const float* __restrict__ Wg,
                                                   const float* __restrict__ bg) {
    __shared__ float sh[256];
    int p = blockIdx.x;                           // one point per block
    int c = threadIdx.x;
    size_t gid = (size_t)p * 256 + c;
    float sc = g_scale[c];
    float vm = (sc >= 0.f) ? g_vmax[gid] : g_vmin[gid];
    float h = leaky(fmaf(g_u[gid] + vm, sc, g_shift[c]));
    g_h1[gid] = h;
    sh[c] = h * Wg[c];
    __syncthreads();
    #pragma unroll
    for (int o = 128; o; o >>= 1) {
        if (c < o) sh[c] += sh[c + o];
        __syncthreads();
    }
    if (c == 0) {
        float gg = sh[0] + bg[0];
        g_gate[p] = gg > 0.f ? gg : 0.f;
    }
}

__global__ void softmax_k() {
    int b = blockIdx.x, t = threadIdx.x;
    __shared__ float sh[256];
    const float* gp = g_gate + (b << 12);
    float* ap = g_alpha + (b << 12);
    float mx = -FINF;
    for (int s = 0; s < 16; s++) mx = fmaxf(mx, gp[t + (s << 8)]);
    sh[t] = mx; __syncthreads();
    for (int o = 128; o; o >>= 1) { if (t < o) sh[t] = fmaxf(sh[t], sh[t + o]); __syncthreads(); }
    float M = sh[0];
    __syncthreads();
    float sum = 0.f;
    for (int s = 0; s < 16; s++) {
        int j = t + (s << 8);
        float e = expf(gp[j] - M);
        ap[j] = e;
        sum += e;
    }
    sh[t] = sum; __syncthreads();
    for (int o = 128; o; o >>= 1) { if (t < o) sh[t] += sh[t + o]; __syncthreads(); }
    float inv = 1.f / sh[0];
    for (int s = 0; s < 16; s++) ap[t + (s << 8)] *= inv;
}

// ---------------- fused feat GEMM + weighted pooling --------------------------
__global__ __launch_bounds__(256) void pool_k(const float* __restrict__ Wf,
                                              const float* __restrict__ bf) {
    int b = blockIdx.x;
    int t = threadIdx.x;
    int ch = blockIdx.y * 256 + t;
    int slab = blockIdx.z;
    __shared__ float hr[16][256];
    __shared__ float al[16];
    float acc = 0.f;
    float bfc = bf[ch];
    for (int gidx = 0; gidx < 8; gidx++) {
        int nb = (slab << 7) + (gidx << 4);
        __syncthreads();
        #pragma unroll
        for (int s = 0; s < 16; s++)
            hr[s][t] = g_h1[((size_t)(b << 12) + nb + s) * 256 + t];
        if (t < 16) al[t] = g_alpha[(b << 12) + nb + t];
        __syncthreads();
        float sacc[16];
        #pragma unroll
        for (int r = 0; r < 16; r++) sacc[r] = bfc;
        #pragma unroll 4
        for (int d = 0; d < 256; d += 4) {
            float w0 = Wf[(d + 0) * 512 + ch];
            float w1 = Wf[(d + 1) * 512 + ch];
            float w2 = Wf[(d + 2) * 512 + ch];
            float w3 = Wf[(d + 3) * 512 + ch];
            #pragma unroll
            for (int r = 0; r < 16; r++) {
                float4 hv = *(const float4*)&hr[r][d];
                sacc[r] = fmaf(hv.x, w0, fmaf(hv.y, w1, fmaf(hv.z, w2, fmaf(hv.w, w3, sacc[r]))));
            }
        }
        #pragma unroll
        for (int r = 0; r < 16; r++) {
            float f = sacc[r] > 0.f ? sacc[r] : 0.f;
            acc = fmaf(al[r], f, acc);
        }
    }
    g_pool[((slab << 2) + b) * 512 + ch] = acc;
}

__global__ void poolred_k() {
    int gid = blockIdx.x * 256 + threadIdx.x;  // BB*512
    if (gid >= BB * 512) return;
    int b = gid >> 9, ch = gid & 511;
    float s = 0.f;
    for (int sl = 0; sl < 32; sl++) s += g_pool[((sl << 2) + b) * 512 + ch];
    g_pooled[gid] = s;
}

__global__ void final_k(const float* __restrict__ Wl, const float* __restrict__ bl,
                        float* __restrict__ out) {
    int b = blockIdx.x, o = threadIdx.x;
    const float* p = g_pooled + b * 512;
    float s = bl[o];
    #pragma unroll 8
    for (int f = 0; f < 512; f++) s = fmaf(p[f], Wl[f * 256 + o], s);
    out[b * 256 + o] = s;
}

// ---------------- launch ------------------------------------------------------
extern "C" void kernel_launch(void* const* d_in, const int* in_sizes, int n_in,
                              void* d_out, int out_size) {
    (void)in_sizes; (void)n_in; (void)out_size;
    const float* x   = (const float*)d_in[0];
    const float* Wt0 = (const float*)d_in[1];
    const float* Wp0 = (const float*)d_in[3];
    const float* g0  = (const float*)d_in[5];
    const float* be0 = (const float*)d_in[6];
    const float* Wt1 = (const float*)d_in[7];
    const float* Wp1 = (const float*)d_in[9];
    const float* g1  = (const float*)d_in[11];
    const float* be1 = (const float*)d_in[12];
    const float* Wg  = (const float*)d_in[13];
    const float* bg  = (const float*)d_in[14];
    const float* Wf  = (const float*)d_in[15];
    const float* bf  = (const float*)d_in[16];
    const float* Wl  = (const float*)d_in[17];
    const float* bl  = (const float*)d_in[18];
    float* out = (float*)d_out;

    // ---- layer 0 ----
    init_k<<<NPTS * 64 / 256, 256>>>(x, Wt0, Wp0, Wt1, Wp1);
    knn0_k<<<NPTS / 8, 256>>>();
    gather_k<64><<<STATS_BLOCKS, 256>>>();
    fin_k<64><<<64, 256>>>(g0, be0);
    finish64_k<<<NPTS * 64 / 256, 256>>>();

    // ---- layer 1 ----
    gemm16_k<<<NPTS / 16, 256>>>(Wt1);               // u1, v1, norms fused
    dist_gemm_k<<<dim3(2080, BB), 256>>>();
    knn1_k<<<NPTS / 8, 256>>>();
    gather_k<256><<<STATS_BLOCKS, 256>>>();
    fin_k<256><<<256, 256>>>(g1, be1);
    finish256_k<<<NPTS, 256>>>(Wg, bg);              // h1 + gate fused

    // ---- attention pooling + final linear ----
    softmax_k<<<BB, 256>>>();
    pool_k<<<dim3(BB, 2, 32), 256>>>(Wf, bf);
    poolred_k<<<8, 256>>>();
    final_k<<<BB, 256>>>(Wl, bl, out);
}

// round 15
// speedup vs baseline: 1.1824x; 1.1065x over previous
#include <cuda_runtime.h>
#include <math.h>

#define BB 4
#define NN 4096
#define KK 20
#define NPTS (BB*NN)            // 16384
#define EDG  (NPTS*KK)          // 327680
#define STATS_BLOCKS 512
#define FULLM 0xffffffffu

#define FINF __int_as_float(0x7f800000)
#define NINF __int_as_float(0xff800000)
#define ULLMAX 0xFFFFFFFFFFFFFFFFULL

// ---------------- scratch (device globals; no allocations allowed) ----------
__device__ float g_dist[(size_t)BB * NN * NN];      // float distances (layer 1)
__device__ float4 g_x4[NPTS];                        // packed (x,y,z,|x|^2)
__device__ float g_d2[NPTS];
__device__ int   g_idx[NPTS * KK];
__device__ float g_u[NPTS * 256];
__device__ float g_v[NPTS * 256];
__device__ float g_vmax[NPTS * 256];
__device__ float g_vmin[NPTS * 256];
__device__ float g_h0[NPTS * 64];
__device__ float g_h1[NPTS * 256];
__device__ float g_Wd1[64 * 256];
__device__ float g_part[STATS_BLOCKS * 2 * 256];
__device__ float g_scale[256];
__device__ float g_shift[256];
__device__ float g_gate[NPTS];
__device__ float g_alpha[NPTS];
__device__ float g_pool[32 * BB * 512];
__device__ float g_pooled[BB * 512];

static __device__ __forceinline__ float leaky(float v) { return v > 0.f ? v : 0.2f * v; }

// float -> order-preserving uint (ascending float == ascending uint)
static __device__ __forceinline__ unsigned okey(float f) {
    unsigned u = __float_as_uint(f);
    return u ^ ((unsigned)(((int)u) >> 31) | 0x80000000u);
}

// round fp32 -> tf32 (rna), returned as float bit-pattern
static __device__ __forceinline__ float tf32r(float x) {
    unsigned r;
    asm("cvt.rna.tf32.f32 %0, %1;" : "=r"(r) : "f"(x));
    return __uint_as_float(r);
}

// m16n8k8 tf32 MMA, accumulate in-place
static __device__ __forceinline__ void mma_tf32(float* d, const unsigned* a,
                                                const unsigned* b) {
    asm volatile(
        "mma.sync.aligned.m16n8k8.row.col.f32.tf32.tf32.f32 "
        "{%0,%1,%2,%3}, {%4,%5,%6,%7}, {%8,%9}, {%0,%1,%2,%3};\n"
        : "+f"(d[0]), "+f"(d[1]), "+f"(d[2]), "+f"(d[3])
        : "r"(a[0]), "r"(a[1]), "r"(a[2]), "r"(a[3]), "r"(b[0]), "r"(b[1]));
}

// ---------------- warp bitonic sorts ------------------------------------------
template <int NR>
static __device__ __forceinline__ void wsortf(float* v, int lane) {
    const int N = NR * 32;
    #pragma unroll
    for (int k = 2; k <= N; k <<= 1) {
        #pragma unroll
        for (int j = k >> 1; j > 0; j >>= 1) {
            if (j >= 32) {
                int rj = j >> 5;
                #pragma unroll
                for (int rr = 0; rr < NR; rr++) {
                    int pr = rr ^ rj;
                    if (pr > rr) {
                        int p = rr * 32 + lane;
                        bool asc = ((p & k) == 0);
                        float a = v[rr], b = v[pr];
                        float mn = fminf(a, b), mx = fmaxf(a, b);
                        v[rr] = asc ? mn : mx;
                        v[pr] = asc ? mx : mn;
                    }
                }
            } else {
                #pragma unroll
                for (int rr = 0; rr < NR; rr++) {
                    int p = rr * 32 + lane;
                    bool asc = ((p & k) == 0);
                    bool lower = ((lane & j) == 0);
                    float o = __shfl_xor_sync(FULLM, v[rr], j);
                    bool keepmin = (asc == lower);
                    float mn = fminf(v[rr], o), mx = fmaxf(v[rr], o);
                    v[rr] = keepmin ? mn : mx;
                }
            }
        }
    }
}

template <int NR>
static __device__ __forceinline__ void wsortu64(unsigned long long* v, int lane) {
    const int N = NR * 32;
    #pragma unroll
    for (int k = 2; k <= N; k <<= 1) {
        #pragma unroll
        for (int j = k >> 1; j > 0; j >>= 1) {
            if (j >= 32) {
                int rj = j >> 5;
                #pragma unroll
                for (int rr = 0; rr < NR; rr++) {
                    int pr = rr ^ rj;
                    if (pr > rr) {
                        int p = rr * 32 + lane;
                        bool asc = ((p & k) == 0);
                        unsigned long long a = v[rr], b = v[pr];
                        unsigned long long mn = a < b ? a : b;
                        unsigned long long mx = a < b ? b : a;
                        v[rr] = asc ? mn : mx;
                        v[pr] = asc ? mx : mn;
                    }
                }
            } else {
                #pragma unroll
                for (int rr = 0; rr < NR; rr++) {
                    int p = rr * 32 + lane;
                    bool asc = ((p & k) == 0);
                    bool lower = ((lane & j) == 0);
                    unsigned long long o = __shfl_xor_sync(FULLM, v[rr], j);
                    bool keepmin = (asc == lower);
                    unsigned long long mn = v[rr] < o ? v[rr] : o;
                    unsigned long long mx = v[rr] < o ? o : v[rr];
                    v[rr] = keepmin ? mn : mx;
                }
            }
        }
    }
}

// ---------------- fallback streaming top-32 (exact, rare) --------------------
static __device__ __forceinline__ unsigned long long wmax64(unsigned long long m) {
    #pragma unroll
    for (int o = 16; o; o >>= 1) {
        unsigned long long ov = __shfl_xor_sync(FULLM, m, o);
        m = m > ov ? m : ov;
    }
    return m;
}

static __device__ __forceinline__ void winsert(unsigned long long c,
                                               unsigned long long& sc,
                                               unsigned long long& tau,
                                               int lane) {
    unsigned bal = __ballot_sync(FULLM, c < tau);
    while (bal) {
        int src = __ffs(bal) - 1;
        bal &= bal - 1;
        unsigned long long cn = __shfl_sync(FULLM, c, src);
        if (cn < tau) {
            unsigned eq = __ballot_sync(FULLM, sc == tau);
            if (lane == __ffs(eq) - 1) sc = cn;
            tau = wmax64(sc);
        }
    }
}

static __device__ __forceinline__ void wfinish(unsigned long long sc, int lane, int* out) {
    unsigned long long v1[1] = {sc};
    wsortu64<1>(v1, lane);
    if (lane < KK) out[lane] = (int)(v1[0] & 0xffffffffu);
}

// sort <=128 composites already in smem buf, emit KK indices
static __device__ __forceinline__ bool buf_finish(unsigned long long* bufw, int cnt,
                                                  int lane, int* out) {
    if (cnt > 128) return false;
    if (cnt <= 64) {
        unsigned long long e[2];
        e[0] = (lane < cnt) ? bufw[lane] : ULLMAX;
        e[1] = (lane + 32 < cnt) ? bufw[lane + 32] : ULLMAX;
        wsortu64<2>(e, lane);
        if (lane < KK) out[lane] = (int)(e[0] & 0xffffffffu);
    } else {
        unsigned long long e[4];
        #pragma unroll
        for (int rr = 0; rr < 4; rr++)
            e[rr] = (rr * 32 + lane < cnt) ? bufw[rr * 32 + lane] : ULLMAX;
        wsortu64<4>(e, lane);
        if (lane < KK) out[lane] = (int)(e[0] & 0xffffffffu);
    }
    return true;
}

// ---------------- fused init: pack x4, u0/v0, Wd1 ----------------------------
__global__ void init_k(const float* __restrict__ x,
                       const float* __restrict__ Wt0, const float* __restrict__ Wp0,
                       const float* __restrict__ Wt1, const float* __restrict__ Wp1) {
    int gid = blockIdx.x * 256 + threadIdx.x;   // NPTS*64 total
    int r = gid >> 6, c = gid & 63;
    float x0 = x[r * 3], x1 = x[r * 3 + 1], x2 = x[r * 3 + 2];
    float u = x0 * Wt0[c] + x1 * Wt0[64 + c] + x2 * Wt0[128 + c];
    float p = x0 * Wp0[c] + x1 * Wp0[64 + c] + x2 * Wp0[128 + c];
    g_u[gid] = u;
    g_v[gid] = p - u;
    if (gid < NPTS) {
        float a = x[gid * 3], b = x[gid * 3 + 1], cc = x[gid * 3 + 2];
        g_x4[gid] = make_float4(a, b, cc, a * a + b * b + cc * cc);
    }
    if (gid < 64 * 256) g_Wd1[gid] = Wp1[gid] - Wt1[gid];
}

// ---------------- fused 16-row (64->256) GEMM + h0 norms ---------------------
__global__ __launch_bounds__(256) void gemm16_k(const float* __restrict__ Wt1) {
    __shared__ float hs[16 * 64];
    int r0 = blockIdx.x * 16;
    int t = threadIdx.x;
    #pragma unroll
    for (int s = 0; s < 4; s++) {
        int l = t + (s << 8);
        hs[l] = g_h0[(size_t)r0 * 64 + l];
    }
    __syncthreads();
    {
        int w = t >> 5, lane = t & 31;
        #pragma unroll
        for (int rr = 0; rr < 2; rr++) {
            int r = w * 2 + rr;
            float a = hs[r * 64 + lane], b = hs[r * 64 + lane + 32];
            float s = a * a + b * b;
            #pragma unroll
            for (int o = 16; o; o >>= 1) s += __shfl_down_sync(FULLM, s, o);
            if (lane == 0) g_d2[r0 + r] = s;
        }
    }
    float au[16], av[16];
    #pragma unroll
    for (int r = 0; r < 16; r++) { au[r] = 0.f; av[r] = 0.f; }
    #pragma unroll 4
    for (int d = 0; d < 64; d++) {
        float wu = Wt1[d * 256 + t];
        float wv = g_Wd1[d * 256 + t];
        #pragma unroll
        for (int r = 0; r < 16; r++) {
            float h = hs[r * 64 + d];
            au[r] = fmaf(h, wu, au[r]);
            av[r] = fmaf(h, wv, av[r]);
        }
    }
    #pragma unroll
    for (int r = 0; r < 16; r++) {
        g_u[(size_t)(r0 + r) * 256 + t] = au[r];
        g_v[(size_t)(r0 + r) * 256 + t] = av[r];
    }
}

// ---------------- distance GEMM via tf32 tensor cores -------------------------
// 128x128 tile per block, triangular grid over 32x32 tiles (528 per batch).
static __device__ __forceinline__ int tri_start32(int ti) {
    return ti * 32 - (ti * (ti - 1)) / 2;
}

__global__ __launch_bounds__(256) void dist_tc_k() {
    __shared__ float smem_buf[2 * 128 * 36];        // 36 KB
    float (*As)[36] = (float(*)[36])smem_buf;
    float (*Bs)[36] = (float(*)[36])(smem_buf + 128 * 36);
    const int b = blockIdx.y;
    int l = blockIdx.x;                              // 0..527
    int ti = (int)((65.0f - sqrtf(65.0f * 65.0f - 8.0f * (float)l)) * 0.5f);
    if (ti > 31) ti = 31;
    while (ti < 31 && tri_start32(ti + 1) <= l) ti++;
    while (ti > 0 && tri_start32(ti) > l) ti--;
    int tj = ti + (l - tri_start32(ti));
    const int i0 = ti * 128, j0 = tj * 128;
    const bool diag = (ti == tj);
    const float* hb = g_h0 + (size_t)b * NN * 64;
    int t = threadIdx.x;
    int w = t >> 5, lane = t & 31;
    int wr = w >> 1, wc = w & 1;                     // warp tile: rows wr*32, cols wc*64
    int lq = lane & 3, lr = lane >> 2;

    float acc[2][8][4];
    #pragma unroll
    for (int mt = 0; mt < 2; mt++)
        #pragma unroll
        for (int nt = 0; nt < 8; nt++)
            #pragma unroll
            for (int q = 0; q < 4; q++) acc[mt][nt][q] = 0.f;

    #pragma unroll
    for (int kc = 0; kc < 2; kc++) {
        if (kc) __syncthreads();
        #pragma unroll
        for (int idx = t; idx < 128 * 8; idx += 256) {
            int r = idx >> 3, c4 = (idx & 7) << 2;
            float4 va = *(const float4*)&hb[(size_t)(i0 + r) * 64 + kc * 32 + c4];
            float4 vb = *(const float4*)&hb[(size_t)(j0 + r) * 64 + kc * 32 + c4];
            *(float4*)&As[r][c4] = make_float4(tf32r(va.x), tf32r(va.y), tf32r(va.z), tf32r(va.w));
            *(float4*)&Bs[r][c4] = make_float4(tf32r(vb.x), tf32r(vb.y), tf32r(vb.z), tf32r(vb.w));
        }
        __syncthreads();
        #pragma unroll
        for (int ks = 0; ks < 4; ks++) {
            int kk = ks * 8;
            unsigned af[2][4], bf[8][2];
            #pragma unroll
            for (int mt = 0; mt < 2; mt++) {
                int ar = wr * 32 + mt * 16 + lr;
                af[mt][0] = __float_as_uint(As[ar][kk + lq]);
                af[mt][1] = __float_as_uint(As[ar + 8][kk + lq]);
                af[mt][2] = __float_as_uint(As[ar][kk + lq + 4]);
                af[mt][3] = __float_as_uint(As[ar + 8][kk + lq + 4]);
            }
            #pragma unroll
            for (int nt = 0; nt < 8; nt++) {
                int bn = wc * 64 + nt * 8 + lr;
                bf[nt][0] = __float_as_uint(Bs[bn][kk + lq]);
                bf[nt][1] = __float_as_uint(Bs[bn][kk + lq + 4]);
            }
            #pragma unroll
            for (int mt = 0; mt < 2; mt++)
                #pragma unroll
                for (int nt = 0; nt < 8; nt++)
                    mma_tf32(acc[mt][nt], af[mt], bf[nt]);
        }
    }

    const float* n2 = g_d2 + b * NN;
    // direct writes (tile [i0,j0])
    #pragma unroll
    for (int mt = 0; mt < 2; mt++) {
        int r1 = i0 + wr * 32 + mt * 16 + lr;
        float ni1 = n2[r1], ni2 = n2[r1 + 8];
        #pragma unroll
        for (int nt = 0; nt < 8; nt++) {
            int c = j0 + wc * 64 + nt * 8 + 2 * lq;
            float njc = n2[c], njc1 = n2[c + 1];
            float d0 = ni1 + njc  - 2.f * acc[mt][nt][0];
            float d1 = ni1 + njc1 - 2.f * acc[mt][nt][1];
            float d2 = ni2 + njc  - 2.f * acc[mt][nt][2];
            float d3 = ni2 + njc1 - 2.f * acc[mt][nt][3];
            if (diag) {
                if (r1 == c)         d0 = NINF;
                if (r1 == c + 1)     d1 = NINF;
                if (r1 + 8 == c)     d2 = NINF;
                if (r1 + 8 == c + 1) d3 = NINF;
            }
            *(float2*)&g_dist[((size_t)(b * NN + r1)) * NN + c]     = make_float2(d0, d1);
            *(float2*)&g_dist[((size_t)(b * NN + r1 + 8)) * NN + c] = make_float2(d2, d3);
        }
    }
    if (!diag) {
        // mirror via smem transpose staging, two 64-col halves
        float* scr = smem_buf;                       // reuse (64 x 132 <= 9216 floats)
        #pragma unroll
        for (int half = 0; half < 2; half++) {
            __syncthreads();
            if (wc == half) {
                #pragma unroll
                for (int mt = 0; mt < 2; mt++) {
                    int m = wr * 32 + mt * 16 + lr;
                    int r1 = i0 + m;
                    float ni1 = n2[r1], ni2 = n2[r1 + 8];
                    #pragma unroll
                    for (int nt = 0; nt < 8; nt++) {
                        int nn = nt * 8 + 2 * lq;
                        int c = j0 + half * 64 + nn;
                        float njc = n2[c], njc1 = n2[c + 1];
                        scr[nn * 132 + m]           = ni1 + njc  - 2.f * acc[mt][nt][0];
                        scr[(nn + 1) * 132 + m]     = ni1 + njc1 - 2.f * acc[mt][nt][1];
                        scr[nn * 132 + m + 8]       = ni2 + njc  - 2.f * acc[mt][nt][2];
                        scr[(nn + 1) * 132 + m + 8] = ni2 + njc1 - 2.f * acc[mt][nt][3];
                    }
                }
            }
            __syncthreads();
            #pragma unroll
            for (int idx = t; idx < 64 * 128; idx += 256) {
                int nr = idx >> 7, mc = idx & 127;
                g_dist[((size_t)(b * NN + j0 + half * 64 + nr)) * NN + i0 + mc] =
                    scr[nr * 132 + mc];
            }
        }
    }
}

// ---------------- knn0: f32 pass1 + ballot-compact pass2 ---------------------
__global__ __launch_bounds__(256) void knn0_k() {
    __shared__ float4 pts[1024];                    // 16 KB
    __shared__ unsigned long long buf[8][128];      // 8 KB
    int t = threadIdx.x, w = t >> 5, lane = t & 31;
    int row = blockIdx.x * 8 + w;
    int base = row & ~(NN - 1);
    float4 me = g_x4[row];

    float m0 = FINF, m1 = FINF;
    #pragma unroll 1
    for (int chunk = 0; chunk < 4; chunk++) {
        __syncthreads();
        #pragma unroll
        for (int i = 0; i < 4; i++)
            pts[t + (i << 8)] = g_x4[base + (chunk << 10) + t + (i << 8)];
        __syncthreads();
        #pragma unroll 4
        for (int it = 0; it < 32; it++) {
            float4 p = pts[(it << 5) + lane];
            float dot = me.x * p.x + me.y * p.y + me.z * p.z;
            float d = me.w + p.w - 2.f * dot;
            if (d < m0) { m1 = m0; m0 = d; }
            else if (d < m1) { m1 = d; }
        }
    }
    float v2[2] = {m0, m1};
    wsortf<2>(v2, lane);
    float tau = __shfl_sync(FULLM, v2[0], 31);

    int cnt = 0;
    #pragma unroll 1
    for (int chunk = 0; chunk < 4; chunk++) {
        __syncthreads();
        #pragma unroll
        for (int i = 0; i < 4; i++)
            pts[t + (i << 8)] = g_x4[base + (chunk << 10) + t + (i << 8)];
        __syncthreads();
        #pragma unroll 4
        for (int it = 0; it < 32; it++) {
            int jl = (it << 5) + lane;
            float4 p = pts[jl];
            float dot = me.x * p.x + me.y * p.y + me.z * p.z;
            float d = me.w + p.w - 2.f * dot;
            unsigned mask = __ballot_sync(FULLM, d <= tau);
            if (d <= tau) {
                int pos = cnt + __popc(mask & ((1u << lane) - 1));
                if (pos < 128)
                    buf[w][pos] = ((unsigned long long)okey(d) << 32)
                                | (unsigned)((chunk << 10) + jl);
            }
            cnt += __popc(mask);
        }
    }
    int* out = g_idx + row * KK;
    if (!buf_finish(buf[w], cnt, lane, out)) {
        unsigned long long sc, tau2;
        {
            float4 p = g_x4[base + lane];
            float dot = me.x * p.x + me.y * p.y + me.z * p.z;
            float d = me.w + p.w - 2.f * dot;
            sc = ((unsigned long long)okey(d) << 32) | (unsigned)lane;
            tau2 = wmax64(sc);
        }
        for (int it = 1; it < 128; it++) {
            int j = (it << 5) + lane;
            float4 p = g_x4[base + j];
            float dot = me.x * p.x + me.y * p.y + me.z * p.z;
            float d = me.w + p.w - 2.f * dot;
            unsigned long long c = ((unsigned long long)okey(d) << 32) | (unsigned)j;
            winsert(c, sc, tau2, lane);
        }
        wfinish(sc, lane, out);
    }
}

// ---------------- knn1: f32 pass1 + ballot-compact pass2 over dist rows ------
__global__ __launch_bounds__(256) void knn1_k() {
    __shared__ unsigned long long buf[8][128];      // 8 KB
    int t = threadIdx.x, w = t >> 5, lane = t & 31;
    int row = blockIdx.x * 8 + w;
    const float4* dr = (const float4*)(g_dist + (size_t)row * NN);

    float m0 = FINF, m1 = FINF;
    #pragma unroll 4
    for (int it = 0; it < 32; it++) {
        float4 dv = __ldg(&dr[(it << 5) + lane]);
        if (dv.x < m0) { m1 = m0; m0 = dv.x; } else if (dv.x < m1) m1 = dv.x;
        if (dv.y < m0) { m1 = m0; m0 = dv.y; } else if (dv.y < m1) m1 = dv.y;
        if (dv.z < m0) { m1 = m0; m0 = dv.z; } else if (dv.z < m1) m1 = dv.z;
        if (dv.w < m0) { m1 = m0; m0 = dv.w; } else if (dv.w < m1) m1 = dv.w;
    }
    float v2[2] = {m0, m1};
    wsortf<2>(v2, lane);
    float tau = __shfl_sync(FULLM, v2[0], 31);

    int cnt = 0;
    #pragma unroll 2
    for (int it = 0; it < 32; it++) {
        int j4 = (it << 5) + lane;
        float4 dv = __ldg(&dr[j4]);
        int jb = j4 << 2;
        float ds[4] = {dv.x, dv.y, dv.z, dv.w};
        #pragma unroll
        for (int q = 0; q < 4; q++) {
            float d = ds[q];
            unsigned mask = __ballot_sync(FULLM, d <= tau);
            if (d <= tau) {
                int pos = cnt + __popc(mask & ((1u << lane) - 1));
                if (pos < 128)
                    buf[w][pos] = ((unsigned long long)okey(d) << 32) | (unsigned)(jb + q);
            }
            cnt += __popc(mask);
        }
    }
    int* out = g_idx + row * KK;
    if (!buf_finish(buf[w], cnt, lane, out)) {
        const float* drs = g_dist + (size_t)row * NN;
        unsigned long long sc, tau2;
        {
            sc = ((unsigned long long)okey(drs[lane]) << 32) | (unsigned)lane;
            tau2 = wmax64(sc);
        }
        for (int it = 1; it < 128; it++) {
            int j = (it << 5) + lane;
            unsigned long long c = ((unsigned long long)okey(__ldg(&drs[j])) << 32) | (unsigned)j;
            winsert(c, sc, tau2, lane);
        }
        wfinish(sc, lane, out);
    }
}

// ---------------- fused gather: BN stats + per-point neighbor vmax/vmin ------
template <int C>
__global__ __launch_bounds__(256) void gather_k() {
    constexpr int G = 256 / C;
    int t = threadIdx.x;
    int c = t % C;
    int g = t / C;
    float s = 0.f, s2 = 0.f;
    for (int p = blockIdx.x * G + g; p < NPTS; p += STATS_BLOCKS * G) {
        int b = p >> 12;
        float uc = g_u[(size_t)p * C + c];
        const int* ip = g_idx + p * KK;
        float S = 0.f, Q = 0.f, mx = -FINF, mn = FINF;
        #pragma unroll
        for (int k = 0; k < KK; k++) {
            int j = ip[k];
            float v = g_v[((size_t)((b << 12) + j)) * C + c];
            S += v;
            Q = fmaf(v, v, Q);
            mx = fmaxf(mx, v);
            mn = fminf(mn, v);
        }
        g_vmax[(size_t)p * C + c] = mx;
        g_vmin[(size_t)p * C + c] = mn;
        s += fmaf(20.f, uc, S);
        s2 += fmaf(20.f * uc, uc, fmaf(2.f * uc, S, Q));
    }
    __shared__ float sh[256], sh2[256];
    sh[t] = s; sh2[t] = s2;
    __syncthreads();
    if (t < C) {
        float S = sh[t], S2 = sh2[t];
        #pragma unroll
        for (int gg = 1; gg < G; gg++) { S += sh[gg * C + t]; S2 += sh2[gg * C + t]; }
        g_part[blockIdx.x * (2 * C) + t] = S;
        g_part[blockIdx.x * (2 * C) + C + t] = S2;
    }
}

// ---------------- finalize BN scale/shift: one block per channel -------------
template <int C>
__global__ __launch_bounds__(256) void fin_k(const float* __restrict__ gamma,
                                             const float* __restrict__ beta) {
    int c = blockIdx.x;
    int t = threadIdx.x;
    float S = 0.f, S2 = 0.f;
    #pragma unroll
    for (int bk = t; bk < STATS_BLOCKS; bk += 256) {
        S += g_part[bk * 2 * C + c];
        S2 += g_part[bk * 2 * C + C + c];
    }
    #pragma unroll
    for (int o = 16; o; o >>= 1) {
        S += __shfl_down_sync(FULLM, S, o);
        S2 += __shfl_down_sync(FULLM, S2, o);
    }
    __shared__ float sh[8], sh2[8];
    int w = t >> 5, lane = t & 31;
    if (lane == 0) { sh[w] = S; sh2[w] = S2; }
    __syncthreads();
    if (t == 0) {
        float Sa = 0.f, S2a = 0.f;
        #pragma unroll
        for (int i = 0; i < 8; i++) { Sa += sh[i]; S2a += sh2[i]; }
        const float inv = 1.f / (float)EDG;
        float mu = Sa * inv;
        float var = S2a * inv - mu * mu;
        float sc = gamma[c] * rsqrtf(var + 1e-5f);
        g_scale[c] = sc;
        g_shift[c] = beta[c] - mu * sc;
    }
}

// ---------------- finish layer0: h0 = leaky(...) ------------------------------
__global__ void finish64_k() {
    int gid = blockIdx.x * 256 + threadIdx.x;    // NPTS*64
    int c = gid & 63;
    float sc = g_scale[c];
    float vm = (sc >= 0.f) ? g_vmax[gid] : g_vmin[gid];
    float M = g_u[gid] + vm;
    g_h0[gid] = leaky(fmaf(M, sc, g_shift[c]));
}

// ---------------- finish layer1 + fused attention gate -----------------------
__global__ __launch_bounds__(256) void finish256_k(const float* __restrict__ Wg,
                                                   const float* __restrict__ bg) {
    __shared__ float sh[256];
    int p = blockIdx.x;
    int c = threadIdx.x;
    size_t gid = (size_t)p * 256 + c;
    float sc = g_scale[c];
    float vm = (sc >= 0.f) ? g_vmax[gid] : g_vmin[gid];
    float h = leaky(fmaf(g_u[gid] + vm, sc, g_shift[c]));
    g_h1[gid] = h;
    sh[c] = h * Wg[c];
    __syncthreads();
    #pragma unroll
    for (int o = 128; o; o >>= 1) {
        if (c < o) sh[c] += sh[c + o];
        __syncthreads();
    }
    if (c == 0) {
        float gg = sh[0] + bg[0];
        g_gate[p] = gg > 0.f ? gg : 0.f;
    }
}

__global__ void softmax_k() {
    int b = blockIdx.x, t = threadIdx.x;
    __shared__ float sh[256];
    const float* gp = g_gate + (b << 12);
    float* ap = g_alpha + (b << 12);
    float mx = -FINF;
    for (int s = 0; s < 16; s++) mx = fmaxf(mx, gp[t + (s << 8)]);
    sh[t] = mx; __syncthreads();
    for (int o = 128; o; o >>= 1) { if (t < o) sh[t] = fmaxf(sh[t], sh[t + o]); __syncthreads(); }
    float M = sh[0];
    __syncthreads();
    float sum = 0.f;
    for (int s = 0; s < 16; s++) {
        int j = t + (s << 8);
        float e = expf(gp[j] - M);
        ap[j] = e;
        sum += e;
    }
    sh[t] = sum; __syncthreads();
    for (int o = 128; o; o >>= 1) { if (t < o) sh[t] += sh[t + o]; __syncthreads(); }
    float inv = 1.f / sh[0];
    for (int s = 0; s < 16; s++) ap[t + (s << 8)] *= inv;
}

// ---------------- fused feat GEMM + weighted pooling --------------------------
__global__ __launch_bounds__(256) void pool_k(const float* __restrict__ Wf,
                                              const float* __restrict__ bf) {
    int b = blockIdx.x;
    int t = threadIdx.x;
    int ch = blockIdx.y * 256 + t;
    int slab = blockIdx.z;
    __shared__ float hr[16][256];
    __shared__ float al[16];
    float acc = 0.f;
    float bfc = bf[ch];
    for (int gidx = 0; gidx < 8; gidx++) {
        int nb = (slab << 7) + (gidx << 4);
        __syncthreads();
        #pragma unroll
        for (int s = 0; s < 16; s++)
            hr[s][t] = g_h1[((size_t)(b << 12) + nb + s) * 256 + t];
        if (t < 16) al[t] = g_alpha[(b << 12) + nb + t];
        __syncthreads();
        float sacc[16];
        #pragma unroll
        for (int r = 0; r < 16; r++) sacc[r] = bfc;
        #pragma unroll 4
        for (int d = 0; d < 256; d += 4) {
            float w0 = Wf[(d + 0) * 512 + ch];
            float w1 = Wf[(d + 1) * 512 + ch];
            float w2 = Wf[(d + 2) * 512 + ch];
            float w3 = Wf[(d + 3) * 512 + ch];
            #pragma unroll
            for (int r = 0; r < 16; r++) {
                float4 hv = *(const float4*)&hr[r][d];
                sacc[r] = fmaf(hv.x, w0, fmaf(hv.y, w1, fmaf(hv.z, w2, fmaf(hv.w, w3, sacc[r]))));
            }
        }
        #pragma unroll
        for (int r = 0; r < 16; r++) {
            float f = sacc[r] > 0.f ? sacc[r] : 0.f;
            acc = fmaf(al[r], f, acc);
        }
    }
    g_pool[((slab << 2) + b) * 512 + ch] = acc;
}

__global__ void poolred_k() {
    int gid = blockIdx.x * 256 + threadIdx.x;  // BB*512
    if (gid >= BB * 512) return;
    int b = gid >> 9, ch = gid & 511;
    float s = 0.f;
    for (int sl = 0; sl < 32; sl++) s += g_pool[((sl << 2) + b) * 512 + ch];
    g_pooled[gid] = s;
}

__global__ void final_k(const float* __restrict__ Wl, const float* __restrict__ bl,
                        float* __restrict__ out) {
    int b = blockIdx.x, o = threadIdx.x;
    const float* p = g_pooled + b * 512;
    float s = bl[o];
    #pragma unroll 8
    for (int f = 0; f < 512; f++) s = fmaf(p[f], Wl[f * 256 + o], s);
    out[b * 256 + o] = s;
}

// ---------------- launch ------------------------------------------------------
extern "C" void kernel_launch(void* const* d_in, const int* in_sizes, int n_in,
                              void* d_out, int out_size) {
    (void)in_sizes; (void)n_in; (void)out_size;
    const float* x   = (const float*)d_in[0];
    const float* Wt0 = (const float*)d_in[1];
    const float* Wp0 = (const float*)d_in[3];
    const float* g0  = (const float*)d_in[5];
    const float* be0 = (const float*)d_in[6];
    const float* Wt1 = (const float*)d_in[7];
    const float* Wp1 = (const float*)d_in[9];
    const float* g1  = (const float*)d_in[11];
    const float* be1 = (const float*)d_in[12];
    const float* Wg  = (const float*)d_in[13];
    const float* bg  = (const float*)d_in[14];
    const float* Wf  = (const float*)d_in[15];
    const float* bf  = (const float*)d_in[16];
    const float* Wl  = (const float*)d_in[17];
    const float* bl  = (const float*)d_in[18];
    float* out = (float*)d_out;

    // ---- layer 0 ----
    init_k<<<NPTS * 64 / 256, 256>>>(x, Wt0, Wp0, Wt1, Wp1);
    knn0_k<<<NPTS / 8, 256>>>();
    gather_k<64><<<STATS_BLOCKS, 256>>>();
    fin_k<64><<<64, 256>>>(g0, be0);
    finish64_k<<<NPTS * 64 / 256, 256>>>();

    // ---- layer 1 ----
    gemm16_k<<<NPTS / 16, 256>>>(Wt1);               // u1, v1, norms fused
    dist_tc_k<<<dim3(528, BB), 256>>>();             // tf32 tensor-core distances
    knn1_k<<<NPTS / 8, 256>>>();
    gather_k<256><<<STATS_BLOCKS, 256>>>();
    fin_k<256><<<256, 256>>>(g1, be1);
    finish256_k<<<NPTS, 256>>>(Wg, bg);              // h1 + gate fused

    // ---- attention pooling + final linear ----
    softmax_k<<<BB, 256>>>();
    pool_k<<<dim3(BB, 2, 32), 256>>>(Wf, bf);
    poolred_k<<<8, 256>>>();
    final_k<<<BB, 256>>>(Wl, bl, out);
}

// round 16
// speedup vs baseline: 1.4482x; 1.2249x over previous
#include <cuda_runtime.h>
#include <math.h>

#define BB 4
#define NN 4096
#define KK 20
#define NPTS (BB*NN)            // 16384
#define EDG  (NPTS*KK)          // 327680
#define STATS_BLOCKS 512
#define FULLM 0xffffffffu

#define FINF __int_as_float(0x7f800000)
#define NINF __int_as_float(0xff800000)
#define ULLMAX 0xFFFFFFFFFFFFFFFFULL

// ---------------- scratch (device globals; no allocations allowed) ----------
__device__ float g_dist[(size_t)BB * NN * NN];      // float distances (layer 1)
__device__ float4 g_x4[NPTS];                        // packed (x,y,z,|x|^2)
__device__ float g_d2[NPTS];
__device__ int   g_idx[NPTS * KK];
__device__ float g_u[NPTS * 256];
__device__ float g_v[NPTS * 256];
__device__ float g_vmax[NPTS * 256];
__device__ float g_vmin[NPTS * 256];
__device__ float g_h0[NPTS * 64];
__device__ float g_h1[NPTS * 256];
__device__ float g_Wd1[64 * 256];
__device__ float g_part[STATS_BLOCKS * 2 * 256];
__device__ float g_scale[256];
__device__ float g_shift[256];
__device__ float g_gate[NPTS];
__device__ float g_alpha[NPTS];
__device__ float g_pool[32 * BB * 512];
__device__ float g_pooled[BB * 512];

static __device__ __forceinline__ float leaky(float v) { return v > 0.f ? v : 0.2f * v; }

// float -> order-preserving uint (ascending float == ascending uint)
static __device__ __forceinline__ unsigned okey(float f) {
    unsigned u = __float_as_uint(f);
    return u ^ ((unsigned)(((int)u) >> 31) | 0x80000000u);
}

// round fp32 -> tf32 (rna), returned as float bit-pattern
static __device__ __forceinline__ float tf32r(float x) {
    unsigned r;
    asm("cvt.rna.tf32.f32 %0, %1;" : "=r"(r) : "f"(x));
    return __uint_as_float(r);
}

// m16n8k8 tf32 MMA, accumulate in-place
static __device__ __forceinline__ void mma_tf32(float* d, const unsigned* a,
                                                const unsigned* b) {
    asm volatile(
        "mma.sync.aligned.m16n8k8.row.col.f32.tf32.tf32.f32 "
        "{%0,%1,%2,%3}, {%4,%5,%6,%7}, {%8,%9}, {%0,%1,%2,%3};\n"
        : "+f"(d[0]), "+f"(d[1]), "+f"(d[2]), "+f"(d[3])
        : "r"(a[0]), "r"(a[1]), "r"(a[2]), "r"(a[3]), "r"(b[0]), "r"(b[1]));
}

// ---------------- warp bitonic sorts ------------------------------------------
template <int NR>
static __device__ __forceinline__ void wsortf(float* v, int lane) {
    const int N = NR * 32;
    #pragma unroll
    for (int k = 2; k <= N; k <<= 1) {
        #pragma unroll
        for (int j = k >> 1; j > 0; j >>= 1) {
            if (j >= 32) {
                int rj = j >> 5;
                #pragma unroll
                for (int rr = 0; rr < NR; rr++) {
                    int pr = rr ^ rj;
                    if (pr > rr) {
                        int p = rr * 32 + lane;
                        bool asc = ((p & k) == 0);
                        float a = v[rr], b = v[pr];
                        float mn = fminf(a, b), mx = fmaxf(a, b);
                        v[rr] = asc ? mn : mx;
                        v[pr] = asc ? mx : mn;
                    }
                }
            } else {
                #pragma unroll
                for (int rr = 0; rr < NR; rr++) {
                    int p = rr * 32 + lane;
                    bool asc = ((p & k) == 0);
                    bool lower = ((lane & j) == 0);
                    float o = __shfl_xor_sync(FULLM, v[rr], j);
                    bool keepmin = (asc == lower);
                    float mn = fminf(v[rr], o), mx = fmaxf(v[rr], o);
                    v[rr] = keepmin ? mn : mx;
                }
            }
        }
    }
}

template <int NR>
static __device__ __forceinline__ void wsortu64(unsigned long long* v, int lane) {
    const int N = NR * 32;
    #pragma unroll
    for (int k = 2; k <= N; k <<= 1) {
        #pragma unroll
        for (int j = k >> 1; j > 0; j >>= 1) {
            if (j >= 32) {
                int rj = j >> 5;
                #pragma unroll
                for (int rr = 0; rr < NR; rr++) {
                    int pr = rr ^ rj;
                    if (pr > rr) {
                        int p = rr * 32 + lane;
                        bool asc = ((p & k) == 0);
                        unsigned long long a = v[rr], b = v[pr];
                        unsigned long long mn = a < b ? a : b;
                        unsigned long long mx = a < b ? b : a;
                        v[rr] = asc ? mn : mx;
                        v[pr] = asc ? mx : mn;
                    }
                }
            } else {
                #pragma unroll
                for (int rr = 0; rr < NR; rr++) {
                    int p = rr * 32 + lane;
                    bool asc = ((p & k) == 0);
                    bool lower = ((lane & j) == 0);
                    unsigned long long o = __shfl_xor_sync(FULLM, v[rr], j);
                    bool keepmin = (asc == lower);
                    unsigned long long mn = v[rr] < o ? v[rr] : o;
                    unsigned long long mx = v[rr] < o ? o : v[rr];
                    v[rr] = keepmin ? mn : mx;
                }
            }
        }
    }
}

// ---------------- fallback streaming top-32 (exact, rare) --------------------
static __device__ __forceinline__ unsigned long long wmax64(unsigned long long m) {
    #pragma unroll
    for (int o = 16; o; o >>= 1) {
        unsigned long long ov = __shfl_xor_sync(FULLM, m, o);
        m = m > ov ? m : ov;
    }
    return m;
}

static __device__ __forceinline__ void winsert(unsigned long long c,
                                               unsigned long long& sc,
                                               unsigned long long& tau,
                                               int lane) {
    unsigned bal = __ballot_sync(FULLM, c < tau);
    while (bal) {
        int src = __ffs(bal) - 1;
        bal &= bal - 1;
        unsigned long long cn = __shfl_sync(FULLM, c, src);
        if (cn < tau) {
            unsigned eq = __ballot_sync(FULLM, sc == tau);
            if (lane == __ffs(eq) - 1) sc = cn;
            tau = wmax64(sc);
        }
    }
}

static __device__ __forceinline__ void wfinish(unsigned long long sc, int lane, int* out) {
    unsigned long long v1[1] = {sc};
    wsortu64<1>(v1, lane);
    if (lane < KK) out[lane] = (int)(v1[0] & 0xffffffffu);
}

// sort <=128 composites already in smem buf, emit KK indices
static __device__ __forceinline__ bool buf_finish(unsigned long long* bufw, int cnt,
                                                  int lane, int* out) {
    if (cnt > 128) return false;
    if (cnt <= 64) {
        unsigned long long e[2];
        e[0] = (lane < cnt) ? bufw[lane] : ULLMAX;
        e[1] = (lane + 32 < cnt) ? bufw[lane + 32] : ULLMAX;
        wsortu64<2>(e, lane);
        if (lane < KK) out[lane] = (int)(e[0] & 0xffffffffu);
    } else {
        unsigned long long e[4];
        #pragma unroll
        for (int rr = 0; rr < 4; rr++)
            e[rr] = (rr * 32 + lane < cnt) ? bufw[rr * 32 + lane] : ULLMAX;
        wsortu64<4>(e, lane);
        if (lane < KK) out[lane] = (int)(e[0] & 0xffffffffu);
    }
    return true;
}

// ---------------- fused init: pack x4, u0/v0, Wd1 ----------------------------
__global__ void init_k(const float* __restrict__ x,
                       const float* __restrict__ Wt0, const float* __restrict__ Wp0,
                       const float* __restrict__ Wt1, const float* __restrict__ Wp1) {
    int gid = blockIdx.x * 256 + threadIdx.x;   // NPTS*64 total
    int r = gid >> 6, c = gid & 63;
    float x0 = x[r * 3], x1 = x[r * 3 + 1], x2 = x[r * 3 + 2];
    float u = x0 * Wt0[c] + x1 * Wt0[64 + c] + x2 * Wt0[128 + c];
    float p = x0 * Wp0[c] + x1 * Wp0[64 + c] + x2 * Wp0[128 + c];
    g_u[gid] = u;
    g_v[gid] = p - u;
    if (gid < NPTS) {
        float a = x[gid * 3], b = x[gid * 3 + 1], cc = x[gid * 3 + 2];
        g_x4[gid] = make_float4(a, b, cc, a * a + b * b + cc * cc);
    }
    if (gid < 64 * 256) g_Wd1[gid] = Wp1[gid] - Wt1[gid];
}

// ---------------- fused 16-row (64->256) GEMM + h0 norms ---------------------
__global__ __launch_bounds__(256) void gemm16_k(const float* __restrict__ Wt1) {
    __shared__ float hs[16 * 64];
    int r0 = blockIdx.x * 16;
    int t = threadIdx.x;
    #pragma unroll
    for (int s = 0; s < 4; s++) {
        int l = t + (s << 8);
        hs[l] = g_h0[(size_t)r0 * 64 + l];
    }
    __syncthreads();
    {
        int w = t >> 5, lane = t & 31;
        #pragma unroll
        for (int rr = 0; rr < 2; rr++) {
            int r = w * 2 + rr;
            float a = hs[r * 64 + lane], b = hs[r * 64 + lane + 32];
            float s = a * a + b * b;
            #pragma unroll
            for (int o = 16; o; o >>= 1) s += __shfl_down_sync(FULLM, s, o);
            if (lane == 0) g_d2[r0 + r] = s;
        }
    }
    float au[16], av[16];
    #pragma unroll
    for (int r = 0; r < 16; r++) { au[r] = 0.f; av[r] = 0.f; }
    #pragma unroll 4
    for (int d = 0; d < 64; d++) {
        float wu = Wt1[d * 256 + t];
        float wv = g_Wd1[d * 256 + t];
        #pragma unroll
        for (int r = 0; r < 16; r++) {
            float h = hs[r * 64 + d];
            au[r] = fmaf(h, wu, au[r]);
            av[r] = fmaf(h, wv, av[r]);
        }
    }
    #pragma unroll
    for (int r = 0; r < 16; r++) {
        g_u[(size_t)(r0 + r) * 256 + t] = au[r];
        g_v[(size_t)(r0 + r) * 256 + t] = av[r];
    }
}

// ---------------- distance GEMM via tf32 tensor cores -------------------------
static __device__ __forceinline__ int tri_start32(int ti) {
    return ti * 32 - (ti * (ti - 1)) / 2;
}

__global__ __launch_bounds__(256) void dist_tc_k() {
    __shared__ float smem_buf[2 * 128 * 36];        // 36 KB
    float (*As)[36] = (float(*)[36])smem_buf;
    float (*Bs)[36] = (float(*)[36])(smem_buf + 128 * 36);
    const int b = blockIdx.y;
    int l = blockIdx.x;                              // 0..527
    int ti = (int)((65.0f - sqrtf(65.0f * 65.0f - 8.0f * (float)l)) * 0.5f);
    if (ti > 31) ti = 31;
    while (ti < 31 && tri_start32(ti + 1) <= l) ti++;
    while (ti > 0 && tri_start32(ti) > l) ti--;
    int tj = ti + (l - tri_start32(ti));
    const int i0 = ti * 128, j0 = tj * 128;
    const bool diag = (ti == tj);
    const float* hb = g_h0 + (size_t)b * NN * 64;
    int t = threadIdx.x;
    int w = t >> 5, lane = t & 31;
    int wr = w >> 1, wc = w & 1;
    int lq = lane & 3, lr = lane >> 2;

    float acc[2][8][4];
    #pragma unroll
    for (int mt = 0; mt < 2; mt++)
        #pragma unroll
        for (int nt = 0; nt < 8; nt++)
            #pragma unroll
            for (int q = 0; q < 4; q++) acc[mt][nt][q] = 0.f;

    #pragma unroll
    for (int kc = 0; kc < 2; kc++) {
        if (kc) __syncthreads();
        #pragma unroll
        for (int idx = t; idx < 128 * 8; idx += 256) {
            int r = idx >> 3, c4 = (idx & 7) << 2;
            float4 va = *(const float4*)&hb[(size_t)(i0 + r) * 64 + kc * 32 + c4];
            float4 vb = *(const float4*)&hb[(size_t)(j0 + r) * 64 + kc * 32 + c4];
            *(float4*)&As[r][c4] = make_float4(tf32r(va.x), tf32r(va.y), tf32r(va.z), tf32r(va.w));
            *(float4*)&Bs[r][c4] = make_float4(tf32r(vb.x), tf32r(vb.y), tf32r(vb.z), tf32r(vb.w));
        }
        __syncthreads();
        #pragma unroll
        for (int ks = 0; ks < 4; ks++) {
            int kk = ks * 8;
            unsigned af[2][4], bf[8][2];
            #pragma unroll
            for (int mt = 0; mt < 2; mt++) {
                int ar = wr * 32 + mt * 16 + lr;
                af[mt][0] = __float_as_uint(As[ar][kk + lq]);
                af[mt][1] = __float_as_uint(As[ar + 8][kk + lq]);
                af[mt][2] = __float_as_uint(As[ar][kk + lq + 4]);
                af[mt][3] = __float_as_uint(As[ar + 8][kk + lq + 4]);
            }
            #pragma unroll
            for (int nt = 0; nt < 8; nt++) {
                int bn = wc * 64 + nt * 8 + lr;
                bf[nt][0] = __float_as_uint(Bs[bn][kk + lq]);
                bf[nt][1] = __float_as_uint(Bs[bn][kk + lq + 4]);
            }
            #pragma unroll
            for (int mt = 0; mt < 2; mt++)
                #pragma unroll
                for (int nt = 0; nt < 8; nt++)
                    mma_tf32(acc[mt][nt], af[mt], bf[nt]);
        }
    }

    const float* n2 = g_d2 + b * NN;
    #pragma unroll
    for (int mt = 0; mt < 2; mt++) {
        int r1 = i0 + wr * 32 + mt * 16 + lr;
        float ni1 = n2[r1], ni2 = n2[r1 + 8];
        #pragma unroll
        for (int nt = 0; nt < 8; nt++) {
            int c = j0 + wc * 64 + nt * 8 + 2 * lq;
            float njc = n2[c], njc1 = n2[c + 1];
            float d0 = ni1 + njc  - 2.f * acc[mt][nt][0];
            float d1 = ni1 + njc1 - 2.f * acc[mt][nt][1];
            float d2 = ni2 + njc  - 2.f * acc[mt][nt][2];
            float d3 = ni2 + njc1 - 2.f * acc[mt][nt][3];
            if (diag) {
                if (r1 == c)         d0 = NINF;
                if (r1 == c + 1)     d1 = NINF;
                if (r1 + 8 == c)     d2 = NINF;
                if (r1 + 8 == c + 1) d3 = NINF;
            }
            *(float2*)&g_dist[((size_t)(b * NN + r1)) * NN + c]     = make_float2(d0, d1);
            *(float2*)&g_dist[((size_t)(b * NN + r1 + 8)) * NN + c] = make_float2(d2, d3);
        }
    }
    if (!diag) {
        float* scr = smem_buf;
        #pragma unroll
        for (int half = 0; half < 2; half++) {
            __syncthreads();
            if (wc == half) {
                #pragma unroll
                for (int mt = 0; mt < 2; mt++) {
                    int m = wr * 32 + mt * 16 + lr;
                    int r1 = i0 + m;
                    float ni1 = n2[r1], ni2 = n2[r1 + 8];
                    #pragma unroll
                    for (int nt = 0; nt < 8; nt++) {
                        int nn = nt * 8 + 2 * lq;
                        int c = j0 + half * 64 + nn;
                        float njc = n2[c], njc1 = n2[c + 1];
                        scr[nn * 132 + m]           = ni1 + njc  - 2.f * acc[mt][nt][0];
                        scr[(nn + 1) * 132 + m]     = ni1 + njc1 - 2.f * acc[mt][nt][1];
                        scr[nn * 132 + m + 8]       = ni2 + njc  - 2.f * acc[mt][nt][2];
                        scr[(nn + 1) * 132 + m + 8] = ni2 + njc1 - 2.f * acc[mt][nt][3];
                    }
                }
            }
            __syncthreads();
            #pragma unroll
            for (int idx = t; idx < 64 * 128; idx += 256) {
                int nr = idx >> 7, mc = idx & 127;
                g_dist[((size_t)(b * NN + j0 + half * 64 + nr)) * NN + i0 + mc] =
                    scr[nr * 132 + mc];
            }
        }
    }
}

// ---------------- knn0: f32 pass1 + ballot-compact pass2 ---------------------
__global__ __launch_bounds__(256) void knn0_k() {
    __shared__ float4 pts[1024];
    __shared__ unsigned long long buf[8][128];
    int t = threadIdx.x, w = t >> 5, lane = t & 31;
    int row = blockIdx.x * 8 + w;
    int base = row & ~(NN - 1);
    float4 me = g_x4[row];

    float m0 = FINF, m1 = FINF;
    #pragma unroll 1
    for (int chunk = 0; chunk < 4; chunk++) {
        __syncthreads();
        #pragma unroll
        for (int i = 0; i < 4; i++)
            pts[t + (i << 8)] = g_x4[base + (chunk << 10) + t + (i << 8)];
        __syncthreads();
        #pragma unroll 4
        for (int it = 0; it < 32; it++) {
            float4 p = pts[(it << 5) + lane];
            float dot = me.x * p.x + me.y * p.y + me.z * p.z;
            float d = me.w + p.w - 2.f * dot;
            if (d < m0) { m1 = m0; m0 = d; }
            else if (d < m1) { m1 = d; }
        }
    }
    float v2[2] = {m0, m1};
    wsortf<2>(v2, lane);
    float tau = __shfl_sync(FULLM, v2[0], 31);

    int cnt = 0;
    #pragma unroll 1
    for (int chunk = 0; chunk < 4; chunk++) {
        __syncthreads();
        #pragma unroll
        for (int i = 0; i < 4; i++)
            pts[t + (i << 8)] = g_x4[base + (chunk << 10) + t + (i << 8)];
        __syncthreads();
        #pragma unroll 4
        for (int it = 0; it < 32; it++) {
            int jl = (it << 5) + lane;
            float4 p = pts[jl];
            float dot = me.x * p.x + me.y * p.y + me.z * p.z;
            float d = me.w + p.w - 2.f * dot;
            unsigned mask = __ballot_sync(FULLM, d <= tau);
            if (d <= tau) {
                int pos = cnt + __popc(mask & ((1u << lane) - 1));
                if (pos < 128)
                    buf[w][pos] = ((unsigned long long)okey(d) << 32)
                                | (unsigned)((chunk << 10) + jl);
            }
            cnt += __popc(mask);
        }
    }
    int* out = g_idx + row * KK;
    if (!buf_finish(buf[w], cnt, lane, out)) {
        unsigned long long sc, tau2;
        {
            float4 p = g_x4[base + lane];
            float dot = me.x * p.x + me.y * p.y + me.z * p.z;
            float d = me.w + p.w - 2.f * dot;
            sc = ((unsigned long long)okey(d) << 32) | (unsigned)lane;
            tau2 = wmax64(sc);
        }
        for (int it = 1; it < 128; it++) {
            int j = (it << 5) + lane;
            float4 p = g_x4[base + j];
            float dot = me.x * p.x + me.y * p.y + me.z * p.z;
            float d = me.w + p.w - 2.f * dot;
            unsigned long long c = ((unsigned long long)okey(d) << 32) | (unsigned)j;
            winsert(c, sc, tau2, lane);
        }
        wfinish(sc, lane, out);
    }
}

// ---------------- knn1: f32 pass1 + ballot-compact pass2 over dist rows ------
__global__ __launch_bounds__(256) void knn1_k() {
    __shared__ unsigned long long buf[8][128];
    int t = threadIdx.x, w = t >> 5, lane = t & 31;
    int row = blockIdx.x * 8 + w;
    const float4* dr = (const float4*)(g_dist + (size_t)row * NN);

    float m0 = FINF, m1 = FINF;
    #pragma unroll 4
    for (int it = 0; it < 32; it++) {
        float4 dv = __ldg(&dr[(it << 5) + lane]);
        if (dv.x < m0) { m1 = m0; m0 = dv.x; } else if (dv.x < m1) m1 = dv.x;
        if (dv.y < m0) { m1 = m0; m0 = dv.y; } else if (dv.y < m1) m1 = dv.y;
        if (dv.z < m0) { m1 = m0; m0 = dv.z; } else if (dv.z < m1) m1 = dv.z;
        if (dv.w < m0) { m1 = m0; m0 = dv.w; } else if (dv.w < m1) m1 = dv.w;
    }
    float v2[2] = {m0, m1};
    wsortf<2>(v2, lane);
    float tau = __shfl_sync(FULLM, v2[0], 31);

    int cnt = 0;
    #pragma unroll 2
    for (int it = 0; it < 32; it++) {
        int j4 = (it << 5) + lane;
        float4 dv = __ldg(&dr[j4]);
        int jb = j4 << 2;
        float ds[4] = {dv.x, dv.y, dv.z, dv.w};
        #pragma unroll
        for (int q = 0; q < 4; q++) {
            float d = ds[q];
            unsigned mask = __ballot_sync(FULLM, d <= tau);
            if (d <= tau) {
                int pos = cnt + __popc(mask & ((1u << lane) - 1));
                if (pos < 128)
                    buf[w][pos] = ((unsigned long long)okey(d) << 32) | (unsigned)(jb + q);
            }
            cnt += __popc(mask);
        }
    }
    int* out = g_idx + row * KK;
    if (!buf_finish(buf[w], cnt, lane, out)) {
        const float* drs = g_dist + (size_t)row * NN;
        unsigned long long sc, tau2;
        {
            sc = ((unsigned long long)okey(drs[lane]) << 32) | (unsigned)lane;
            tau2 = wmax64(sc);
        }
        for (int it = 1; it < 128; it++) {
            int j = (it << 5) + lane;
            unsigned long long c = ((unsigned long long)okey(__ldg(&drs[j])) << 32) | (unsigned)j;
            winsert(c, sc, tau2, lane);
        }
        wfinish(sc, lane, out);
    }
}

// ---------------- fused gather: BN stats + per-point neighbor vmax/vmin ------
template <int C>
__global__ __launch_bounds__(256) void gather_k() {
    constexpr int G = 256 / C;
    int t = threadIdx.x;
    int c = t % C;
    int g = t / C;
    float s = 0.f, s2 = 0.f;
    for (int p = blockIdx.x * G + g; p < NPTS; p += STATS_BLOCKS * G) {
        int b = p >> 12;
        float uc = g_u[(size_t)p * C + c];
        const int* ip = g_idx + p * KK;
        float S = 0.f, Q = 0.f, mx = -FINF, mn = FINF;
        #pragma unroll
        for (int k = 0; k < KK; k++) {
            int j = ip[k];
            float v = g_v[((size_t)((b << 12) + j)) * C + c];
            S += v;
            Q = fmaf(v, v, Q);
            mx = fmaxf(mx, v);
            mn = fminf(mn, v);
        }
        g_vmax[(size_t)p * C + c] = mx;
        g_vmin[(size_t)p * C + c] = mn;
        s += fmaf(20.f, uc, S);
        s2 += fmaf(20.f * uc, uc, fmaf(2.f * uc, S, Q));
    }
    __shared__ float sh[256], sh2[256];
    sh[t] = s; sh2[t] = s2;
    __syncthreads();
    if (t < C) {
        float S = sh[t], S2 = sh2[t];
        #pragma unroll
        for (int gg = 1; gg < G; gg++) { S += sh[gg * C + t]; S2 += sh2[gg * C + t]; }
        g_part[blockIdx.x * (2 * C) + t] = S;
        g_part[blockIdx.x * (2 * C) + C + t] = S2;
    }
}

// ---------------- finalize BN scale/shift: one block per channel -------------
template <int C>
__global__ __launch_bounds__(256) void fin_k(const float* __restrict__ gamma,
                                             const float* __restrict__ beta) {
    int c = blockIdx.x;
    int t = threadIdx.x;
    float S = 0.f, S2 = 0.f;
    #pragma unroll
    for (int bk = t; bk < STATS_BLOCKS; bk += 256) {
        S += g_part[bk * 2 * C + c];
        S2 += g_part[bk * 2 * C + C + c];
    }
    #pragma unroll
    for (int o = 16; o; o >>= 1) {
        S += __shfl_down_sync(FULLM, S, o);
        S2 += __shfl_down_sync(FULLM, S2, o);
    }
    __shared__ float sh[8], sh2[8];
    int w = t >> 5, lane = t & 31;
    if (lane == 0) { sh[w] = S; sh2[w] = S2; }
    __syncthreads();
    if (t == 0) {
        float Sa = 0.f, S2a = 0.f;
        #pragma unroll
        for (int i = 0; i < 8; i++) { Sa += sh[i]; S2a += sh2[i]; }
        const float inv = 1.f / (float)EDG;
        float mu = Sa * inv;
        float var = S2a * inv - mu * mu;
        float sc = gamma[c] * rsqrtf(var + 1e-5f);
        g_scale[c] = sc;
        g_shift[c] = beta[c] - mu * sc;
    }
}

// ---------------- finish layer0: h0 = leaky(...) ------------------------------
__global__ void finish64_k() {
    int gid = blockIdx.x * 256 + threadIdx.x;    // NPTS*64
    int c = gid & 63;
    float sc = g_scale[c];
    float vm = (sc >= 0.f) ? g_vmax[gid] : g_vmin[gid];
    float M = g_u[gid] + vm;
    g_h0[gid] = leaky(fmaf(M, sc, g_shift[c]));
}

// ---------------- finish layer1 + fused attention gate -----------------------
__global__ __launch_bounds__(256) void finish256_k(const float* __restrict__ Wg,
                                                   const float* __restrict__ bg) {
    __shared__ float sh[256];
    int p = blockIdx.x;
    int c = threadIdx.x;
    size_t gid = (size_t)p * 256 + c;
    float sc = g_scale[c];
    float vm = (sc >= 0.f) ? g_vmax[gid] : g_vmin[gid];
    float h = leaky(fmaf(g_u[gid] + vm, sc, g_shift[c]));
    g_h1[gid] = h;
    sh[c] = h * Wg[c];
    __syncthreads();
    #pragma unroll
    for (int o = 128; o; o >>= 1) {
        if (c < o) sh[c] += sh[c + o];
        __syncthreads();
    }
    if (c == 0) {
        float gg = sh[0] + bg[0];
        g_gate[p] = gg > 0.f ? gg : 0.f;
    }
}

__global__ void softmax_k() {
    int b = blockIdx.x, t = threadIdx.x;
    __shared__ float sh[256];
    const float* gp = g_gate + (b << 12);
    float* ap = g_alpha + (b << 12);
    float mx = -FINF;
    for (int s = 0; s < 16; s++) mx = fmaxf(mx, gp[t + (s << 8)]);
    sh[t] = mx; __syncthreads();
    for (int o = 128; o; o >>= 1) { if (t < o) sh[t] = fmaxf(sh[t], sh[t + o]); __syncthreads(); }
    float M = sh[0];
    __syncthreads();
    float sum = 0.f;
    for (int s = 0; s < 16; s++) {
        int j = t + (s << 8);
        float e = expf(gp[j] - M);
        ap[j] = e;
        sum += e;
    }
    sh[t] = sum; __syncthreads();
    for (int o = 128; o; o >>= 1) { if (t < o) sh[t] += sh[t + o]; __syncthreads(); }
    float inv = 1.f / sh[0];
    for (int s = 0; s < 16; s++) ap[t + (s << 8)] *= inv;
}

// ---------------- tf32 tensor-core feat GEMM + weighted pooling ---------------
// block: 128 points x 128 channels.  grid (32 nblk, 4 chblk, BB).
__global__ __launch_bounds__(256) void pool_tc_k(const float* __restrict__ Wf,
                                                 const float* __restrict__ bf) {
    __shared__ float Ah[128][36];           // h1 tile  (tf32), 18 KB
    __shared__ float Bw[128][33];           // Wf^T tile (tf32), 16.9 KB
    __shared__ float als[128];
    __shared__ float part[8][64];
    const int nblk = blockIdx.x, chblk = blockIdx.y, b = blockIdx.z;
    const int n0 = nblk * 128, ch0 = chblk * 128;
    int t = threadIdx.x;
    int w = t >> 5, lane = t & 31;
    int wr = w >> 1, wc = w & 1;
    int lq = lane & 3, lr = lane >> 2;

    if (t < 128) als[t] = g_alpha[(b << 12) + n0 + t];

    float acc[2][8][4];
    #pragma unroll
    for (int mt = 0; mt < 2; mt++)
        #pragma unroll
        for (int nt = 0; nt < 8; nt++)
            #pragma unroll
            for (int q = 0; q < 4; q++) acc[mt][nt][q] = 0.f;

    #pragma unroll 1
    for (int kc = 0; kc < 8; kc++) {        // K chunks of 32
        __syncthreads();
        // h1 tile: 128 rows x 32 d, float4 loads
        #pragma unroll
        for (int idx = t; idx < 128 * 8; idx += 256) {
            int r = idx >> 3, c4 = (idx & 7) << 2;
            float4 va = *(const float4*)&g_h1[((size_t)((b << 12) + n0 + r)) * 256 + kc * 32 + c4];
            *(float4*)&Ah[r][c4] = make_float4(tf32r(va.x), tf32r(va.y), tf32r(va.z), tf32r(va.w));
        }
        // Wf^T tile: Bw[ch][d] = Wf[(kc*32+d)*512 + ch0+ch]
        #pragma unroll
        for (int idx = t; idx < 128 * 32; idx += 256) {
            int c = idx & 127, dd = idx >> 7;
            Bw[c][dd] = tf32r(Wf[(size_t)(kc * 32 + dd) * 512 + ch0 + c]);
        }
        __syncthreads();
        #pragma unroll
        for (int ks = 0; ks < 4; ks++) {
            int kk = ks * 8;
            unsigned af[2][4], bfr[8][2];
            #pragma unroll
            for (int mt = 0; mt < 2; mt++) {
                int ar = wr * 32 + mt * 16 + lr;
                af[mt][0] = __float_as_uint(Ah[ar][kk + lq]);
                af[mt][1] = __float_as_uint(Ah[ar + 8][kk + lq]);
                af[mt][2] = __float_as_uint(Ah[ar][kk + lq + 4]);
                af[mt][3] = __float_as_uint(Ah[ar + 8][kk + lq + 4]);
            }
            #pragma unroll
            for (int nt = 0; nt < 8; nt++) {
                int bn = wc * 64 + nt * 8 + lr;
                bfr[nt][0] = __float_as_uint(Bw[bn][kk + lq]);
                bfr[nt][1] = __float_as_uint(Bw[bn][kk + lq + 4]);
            }
            #pragma unroll
            for (int mt = 0; mt < 2; mt++)
                #pragma unroll
                for (int nt = 0; nt < 8; nt++)
                    mma_tf32(acc[mt][nt], af[mt], bfr[nt]);
        }
    }
    __syncthreads();

    // epilogue: bias + relu + alpha-weight + reduce over points
    #pragma unroll
    for (int nt = 0; nt < 8; nt++) {
        int cE = wc * 64 + nt * 8 + 2 * lq;       // even channel (local)
        float bfe = __ldg(&bf[ch0 + cE]);
        float bfo = __ldg(&bf[ch0 + cE + 1]);
        float se = 0.f, so = 0.f;
        #pragma unroll
        for (int mt = 0; mt < 2; mt++) {
            int rloc = wr * 32 + mt * 16 + lr;
            float a1 = als[rloc], a2 = als[rloc + 8];
            float f0 = acc[mt][nt][0] + bfe; f0 = f0 > 0.f ? f0 : 0.f;
            float f1 = acc[mt][nt][1] + bfo; f1 = f1 > 0.f ? f1 : 0.f;
            float f2 = acc[mt][nt][2] + bfe; f2 = f2 > 0.f ? f2 : 0.f;
            float f3 = acc[mt][nt][3] + bfo; f3 = f3 > 0.f ? f3 : 0.f;
            se = fmaf(a1, f0, fmaf(a2, f2, se));
            so = fmaf(a1, f1, fmaf(a2, f3, so));
        }
        // reduce over lr (lane bits 2..4)
        #pragma unroll
        for (int o = 4; o < 32; o <<= 1) {
            se += __shfl_xor_sync(FULLM, se, o);
            so += __shfl_xor_sync(FULLM, so, o);
        }
        if (lr == 0) {
            part[w][nt * 8 + 2 * lq] = se;
            part[w][nt * 8 + 2 * lq + 1] = so;
        }
    }
    __syncthreads();
    if (t < 128) {
        int cg = t >> 6;                    // col group
        int cl = t & 63;
        float s = part[0 * 2 + cg][cl] + part[1 * 2 + cg][cl]
                + part[2 * 2 + cg][cl] + part[3 * 2 + cg][cl];
        g_pool[((nblk << 2) + b) * 512 + ch0 + t] = s;
    }
}

__global__ void poolred_k() {
    int gid = blockIdx.x * 256 + threadIdx.x;  // BB*512
    if (gid >= BB * 512) return;
    int b = gid >> 9, ch = gid & 511;
    float s = 0.f;
    for (int sl = 0; sl < 32; sl++) s += g_pool[((sl << 2) + b) * 512 + ch];
    g_pooled[gid] = s;
}

__global__ void final_k(const float* __restrict__ Wl, const float* __restrict__ bl,
                        float* __restrict__ out) {
    int b = blockIdx.x, o = threadIdx.x;
    const float* p = g_pooled + b * 512;
    float s = bl[o];
    #pragma unroll 8
    for (int f = 0; f < 512; f++) s = fmaf(p[f], Wl[f * 256 + o], s);
    out[b * 256 + o] = s;
}

// ---------------- launch ------------------------------------------------------
extern "C" void kernel_launch(void* const* d_in, const int* in_sizes, int n_in,
                              void* d_out, int out_size) {
    (void)in_sizes; (void)n_in; (void)out_size;
    const float* x   = (const float*)d_in[0];
    const float* Wt0 = (const float*)d_in[1];
    const float* Wp0 = (const float*)d_in[3];
    const float* g0  = (const float*)d_in[5];
    const float* be0 = (const float*)d_in[6];
    const float* Wt1 = (const float*)d_in[7];
    const float* Wp1 = (const float*)d_in[9];
    const float* g1  = (const float*)d_in[11];
    const float* be1 = (const float*)d_in[12];
    const float* Wg  = (const float*)d_in[13];
    const float* bg  = (const float*)d_in[14];
    const float* Wf  = (const float*)d_in[15];
    const float* bf  = (const float*)d_in[16];
    const float* Wl  = (const float*)d_in[17];
    const float* bl  = (const float*)d_in[18];
    float* out = (float*)d_out;

    // ---- layer 0 ----
    init_k<<<NPTS * 64 / 256, 256>>>(x, Wt0, Wp0, Wt1, Wp1);
    knn0_k<<<NPTS / 8, 256>>>();
    gather_k<64><<<STATS_BLOCKS, 256>>>();
    fin_k<64><<<64, 256>>>(g0, be0);
    finish64_k<<<NPTS * 64 / 256, 256>>>();

    // ---- layer 1 ----
    gemm16_k<<<NPTS / 16, 256>>>(Wt1);
    dist_tc_k<<<dim3(528, BB), 256>>>();
    knn1_k<<<NPTS / 8, 256>>>();
    gather_k<256><<<STATS_BLOCKS, 256>>>();
    fin_k<256><<<256, 256>>>(g1, be1);
    finish256_k<<<NPTS, 256>>>(Wg, bg);

    // ---- attention pooling + final linear ----
    softmax_k<<<BB, 256>>>();
    pool_tc_k<<<dim3(32, 4, BB), 256>>>(Wf, bf);
    poolred_k<<<8, 256>>>();
    final_k<<<BB, 256>>>(Wl, bl, out);
}

// round 17
// speedup vs baseline: 1.4534x; 1.0036x over previous
#include <cuda_runtime.h>
#include <math.h>

#define BB 4
#define NN 4096
#define KK 20
#define NPTS (BB*NN)            // 16384
#define EDG  (NPTS*KK)          // 327680
#define STATS_BLOCKS 512
#define FULLM 0xffffffffu

#define FINF __int_as_float(0x7f800000)
#define NINF __int_as_float(0xff800000)
#define ULLMAX 0xFFFFFFFFFFFFFFFFULL

// ---------------- scratch (device globals; no allocations allowed) ----------
__device__ float g_dist[(size_t)BB * NN * NN];      // float distances (layer 1)
__device__ float4 g_x4[NPTS];                        // packed (x,y,z,|x|^2)
__device__ float g_d2[NPTS];
__device__ int   g_idx[NPTS * KK];
__device__ float g_u[NPTS * 256];
__device__ float g_v[NPTS * 256];
__device__ float g_vmax[NPTS * 256];
__device__ float g_vmin[NPTS * 256];
__device__ float g_h0[NPTS * 64];
__device__ float g_h1[NPTS * 256];
__device__ float g_Wd1[64 * 256];
__device__ float g_part[STATS_BLOCKS * 2 * 256];
__device__ float g_scale[256];
__device__ float g_shift[256];
__device__ float g_gate[NPTS];
__device__ float g_alpha[NPTS];
__device__ float g_pool[32 * BB * 512];
__device__ float g_pooled[BB * 512];

static __device__ __forceinline__ float leaky(float v) { return v > 0.f ? v : 0.2f * v; }

// float -> order-preserving uint (ascending float == ascending uint)
static __device__ __forceinline__ unsigned okey(float f) {
    unsigned u = __float_as_uint(f);
    return u ^ ((unsigned)(((int)u) >> 31) | 0x80000000u);
}

// round fp32 -> tf32 (rna), returned as float bit-pattern
static __device__ __forceinline__ float tf32r(float x) {
    unsigned r;
    asm("cvt.rna.tf32.f32 %0, %1;" : "=r"(r) : "f"(x));
    return __uint_as_float(r);
}

// m16n8k8 tf32 MMA, accumulate in-place
static __device__ __forceinline__ void mma_tf32(float* d, const unsigned* a,
                                                const unsigned* b) {
    asm volatile(
        "mma.sync.aligned.m16n8k8.row.col.f32.tf32.tf32.f32 "
        "{%0,%1,%2,%3}, {%4,%5,%6,%7}, {%8,%9}, {%0,%1,%2,%3};\n"
        : "+f"(d[0]), "+f"(d[1]), "+f"(d[2]), "+f"(d[3])
        : "r"(a[0]), "r"(a[1]), "r"(a[2]), "r"(a[3]), "r"(b[0]), "r"(b[1]));
}

// ---------------- warp bitonic sorts ------------------------------------------
template <int NR>
static __device__ __forceinline__ void wsortf(float* v, int lane) {
    const int N = NR * 32;
    #pragma unroll
    for (int k = 2; k <= N; k <<= 1) {
        #pragma unroll
        for (int j = k >> 1; j > 0; j >>= 1) {
            if (j >= 32) {
                int rj = j >> 5;
                #pragma unroll
                for (int rr = 0; rr < NR; rr++) {
                    int pr = rr ^ rj;
                    if (pr > rr) {
                        int p = rr * 32 + lane;
                        bool asc = ((p & k) == 0);
                        float a = v[rr], b = v[pr];
                        float mn = fminf(a, b), mx = fmaxf(a, b);
                        v[rr] = asc ? mn : mx;
                        v[pr] = asc ? mx : mn;
                    }
                }
            } else {
                #pragma unroll
                for (int rr = 0; rr < NR; rr++) {
                    int p = rr * 32 + lane;
                    bool asc = ((p & k) == 0);
                    bool lower = ((lane & j) == 0);
                    float o = __shfl_xor_sync(FULLM, v[rr], j);
                    bool keepmin = (asc == lower);
                    float mn = fminf(v[rr], o), mx = fmaxf(v[rr], o);
                    v[rr] = keepmin ? mn : mx;
                }
            }
        }
    }
}

template <int NR>
static __device__ __forceinline__ void wsortu64(unsigned long long* v, int lane) {
    const int N = NR * 32;
    #pragma unroll
    for (int k = 2; k <= N; k <<= 1) {
        #pragma unroll
        for (int j = k >> 1; j > 0; j >>= 1) {
            if (j >= 32) {
                int rj = j >> 5;
                #pragma unroll
                for (int rr = 0; rr < NR; rr++) {
                    int pr = rr ^ rj;
                    if (pr > rr) {
                        int p = rr * 32 + lane;
                        bool asc = ((p & k) == 0);
                        unsigned long long a = v[rr], b = v[pr];
                        unsigned long long mn = a < b ? a : b;
                        unsigned long long mx = a < b ? b : a;
                        v[rr] = asc ? mn : mx;
                        v[pr] = asc ? mx : mn;
                    }
                }
            } else {
                #pragma unroll
                for (int rr = 0; rr < NR; rr++) {
                    int p = rr * 32 + lane;
                    bool asc = ((p & k) == 0);
                    bool lower = ((lane & j) == 0);
                    unsigned long long o = __shfl_xor_sync(FULLM, v[rr], j);
                    bool keepmin = (asc == lower);
                    unsigned long long mn = v[rr] < o ? v[rr] : o;
                    unsigned long long mx = v[rr] < o ? o : v[rr];
                    v[rr] = keepmin ? mn : mx;
                }
            }
        }
    }
}

// ---------------- fallback streaming top-32 (exact, rare) --------------------
static __device__ __forceinline__ unsigned long long wmax64(unsigned long long m) {
    #pragma unroll
    for (int o = 16; o; o >>= 1) {
        unsigned long long ov = __shfl_xor_sync(FULLM, m, o);
        m = m > ov ? m : ov;
    }
    return m;
}

static __device__ __forceinline__ void winsert(unsigned long long c,
                                               unsigned long long& sc,
                                               unsigned long long& tau,
                                               int lane) {
    unsigned bal = __ballot_sync(FULLM, c < tau);
    while (bal) {
        int src = __ffs(bal) - 1;
        bal &= bal - 1;
        unsigned long long cn = __shfl_sync(FULLM, c, src);
        if (cn < tau) {
            unsigned eq = __ballot_sync(FULLM, sc == tau);
            if (lane == __ffs(eq) - 1) sc = cn;
            tau = wmax64(sc);
        }
    }
}

static __device__ __forceinline__ void wfinish(unsigned long long sc, int lane, int* out) {
    unsigned long long v1[1] = {sc};
    wsortu64<1>(v1, lane);
    if (lane < KK) out[lane] = (int)(v1[0] & 0xffffffffu);
}

// sort <=128 composites already in smem buf, emit KK indices
static __device__ __forceinline__ bool buf_finish(unsigned long long* bufw, int cnt,
                                                  int lane, int* out) {
    if (cnt > 128) return false;
    if (cnt <= 64) {
        unsigned long long e[2];
        e[0] = (lane < cnt) ? bufw[lane] : ULLMAX;
        e[1] = (lane + 32 < cnt) ? bufw[lane + 32] : ULLMAX;
        wsortu64<2>(e, lane);
        if (lane < KK) out[lane] = (int)(e[0] & 0xffffffffu);
    } else {
        unsigned long long e[4];
        #pragma unroll
        for (int rr = 0; rr < 4; rr++)
            e[rr] = (rr * 32 + lane < cnt) ? bufw[rr * 32 + lane] : ULLMAX;
        wsortu64<4>(e, lane);
        if (lane < KK) out[lane] = (int)(e[0] & 0xffffffffu);
    }
    return true;
}

// ---------------- fused init: pack x4, u0/v0, Wd1 ----------------------------
__global__ void init_k(const float* __restrict__ x,
                       const float* __restrict__ Wt0, const float* __restrict__ Wp0,
                       const float* __restrict__ Wt1, const float* __restrict__ Wp1) {
    int gid = blockIdx.x * 256 + threadIdx.x;   // NPTS*64 total
    int r = gid >> 6, c = gid & 63;
    float x0 = x[r * 3], x1 = x[r * 3 + 1], x2 = x[r * 3 + 2];
    float u = x0 * Wt0[c] + x1 * Wt0[64 + c] + x2 * Wt0[128 + c];
    float p = x0 * Wp0[c] + x1 * Wp0[64 + c] + x2 * Wp0[128 + c];
    g_u[gid] = u;
    g_v[gid] = p - u;
    if (gid < NPTS) {
        float a = x[gid * 3], b = x[gid * 3 + 1], cc = x[gid * 3 + 2];
        g_x4[gid] = make_float4(a, b, cc, a * a + b * b + cc * cc);
    }
    if (gid < 64 * 256) g_Wd1[gid] = Wp1[gid] - Wt1[gid];
}

// ---------------- fused 16-row (64->256) GEMM + h0 norms ---------------------
__global__ __launch_bounds__(256) void gemm16_k(const float* __restrict__ Wt1) {
    __shared__ float hs[16 * 64];
    int r0 = blockIdx.x * 16;
    int t = threadIdx.x;
    #pragma unroll
    for (int s = 0; s < 4; s++) {
        int l = t + (s << 8);
        hs[l] = g_h0[(size_t)r0 * 64 + l];
    }
    __syncthreads();
    {
        int w = t >> 5, lane = t & 31;
        #pragma unroll
        for (int rr = 0; rr < 2; rr++) {
            int r = w * 2 + rr;
            float a = hs[r * 64 + lane], b = hs[r * 64 + lane + 32];
            float s = a * a + b * b;
            #pragma unroll
            for (int o = 16; o; o >>= 1) s += __shfl_down_sync(FULLM, s, o);
            if (lane == 0) g_d2[r0 + r] = s;
        }
    }
    float au[16], av[16];
    #pragma unroll
    for (int r = 0; r < 16; r++) { au[r] = 0.f; av[r] = 0.f; }
    #pragma unroll 4
    for (int d = 0; d < 64; d++) {
        float wu = Wt1[d * 256 + t];
        float wv = g_Wd1[d * 256 + t];
        #pragma unroll
        for (int r = 0; r < 16; r++) {
            float h = hs[r * 64 + d];
            au[r] = fmaf(h, wu, au[r]);
            av[r] = fmaf(h, wv, av[r]);
        }
    }
    #pragma unroll
    for (int r = 0; r < 16; r++) {
        g_u[(size_t)(r0 + r) * 256 + t] = au[r];
        g_v[(size_t)(r0 + r) * 256 + t] = av[r];
    }
}

// ---------------- distance GEMM via tf32 tensor cores -------------------------
static __device__ __forceinline__ int tri_start32(int ti) {
    return ti * 32 - (ti * (ti - 1)) / 2;
}

__global__ __launch_bounds__(256) void dist_tc_k() {
    __shared__ float smem_buf[2 * 128 * 36];        // 36 KB
    float (*As)[36] = (float(*)[36])smem_buf;
    float (*Bs)[36] = (float(*)[36])(smem_buf + 128 * 36);
    const int b = blockIdx.y;
    int l = blockIdx.x;                              // 0..527
    int ti = (int)((65.0f - sqrtf(65.0f * 65.0f - 8.0f * (float)l)) * 0.5f);
    if (ti > 31) ti = 31;
    while (ti < 31 && tri_start32(ti + 1) <= l) ti++;
    while (ti > 0 && tri_start32(ti) > l) ti--;
    int tj = ti + (l - tri_start32(ti));
    const int i0 = ti * 128, j0 = tj * 128;
    const bool diag = (ti == tj);
    const float* hb = g_h0 + (size_t)b * NN * 64;
    int t = threadIdx.x;
    int w = t >> 5, lane = t & 31;
    int wr = w >> 1, wc = w & 1;
    int lq = lane & 3, lr = lane >> 2;

    float acc[2][8][4];
    #pragma unroll
    for (int mt = 0; mt < 2; mt++)
        #pragma unroll
        for (int nt = 0; nt < 8; nt++)
            #pragma unroll
            for (int q = 0; q < 4; q++) acc[mt][nt][q] = 0.f;

    #pragma unroll
    for (int kc = 0; kc < 2; kc++) {
        if (kc) __syncthreads();
        #pragma unroll
        for (int idx = t; idx < 128 * 8; idx += 256) {
            int r = idx >> 3, c4 = (idx & 7) << 2;
            float4 va = *(const float4*)&hb[(size_t)(i0 + r) * 64 + kc * 32 + c4];
            float4 vb = *(const float4*)&hb[(size_t)(j0 + r) * 64 + kc * 32 + c4];
            *(float4*)&As[r][c4] = make_float4(tf32r(va.x), tf32r(va.y), tf32r(va.z), tf32r(va.w));
            *(float4*)&Bs[r][c4] = make_float4(tf32r(vb.x), tf32r(vb.y), tf32r(vb.z), tf32r(vb.w));
        }
        __syncthreads();
        #pragma unroll
        for (int ks = 0; ks < 4; ks++) {
            int kk = ks * 8;
            unsigned af[2][4], bf[8][2];
            #pragma unroll
            for (int mt = 0; mt < 2; mt++) {
                int ar = wr * 32 + mt * 16 + lr;
                af[mt][0] = __float_as_uint(As[ar][kk + lq]);
                af[mt][1] = __float_as_uint(As[ar + 8][kk + lq]);
                af[mt][2] = __float_as_uint(As[ar][kk + lq + 4]);
                af[mt][3] = __float_as_uint(As[ar + 8][kk + lq + 4]);
            }
            #pragma unroll
            for (int nt = 0; nt < 8; nt++) {
                int bn = wc * 64 + nt * 8 + lr;
                bf[nt][0] = __float_as_uint(Bs[bn][kk + lq]);
                bf[nt][1] = __float_as_uint(Bs[bn][kk + lq + 4]);
            }
            #pragma unroll
            for (int mt = 0; mt < 2; mt++)
                #pragma unroll
                for (int nt = 0; nt < 8; nt++)
                    mma_tf32(acc[mt][nt], af[mt], bf[nt]);
        }
    }

    const float* n2 = g_d2 + b * NN;
    #pragma unroll
    for (int mt = 0; mt < 2; mt++) {
        int r1 = i0 + wr * 32 + mt * 16 + lr;
        float ni1 = n2[r1], ni2 = n2[r1 + 8];
        #pragma unroll
        for (int nt = 0; nt < 8; nt++) {
            int c = j0 + wc * 64 + nt * 8 + 2 * lq;
            float njc = n2[c], njc1 = n2[c + 1];
            float d0 = ni1 + njc  - 2.f * acc[mt][nt][0];
            float d1 = ni1 + njc1 - 2.f * acc[mt][nt][1];
            float d2 = ni2 + njc  - 2.f * acc[mt][nt][2];
            float d3 = ni2 + njc1 - 2.f * acc[mt][nt][3];
            if (diag) {
                if (r1 == c)         d0 = NINF;
                if (r1 == c + 1)     d1 = NINF;
                if (r1 + 8 == c)     d2 = NINF;
                if (r1 + 8 == c + 1) d3 = NINF;
            }
            *(float2*)&g_dist[((size_t)(b * NN + r1)) * NN + c]     = make_float2(d0, d1);
            *(float2*)&g_dist[((size_t)(b * NN + r1 + 8)) * NN + c] = make_float2(d2, d3);
        }
    }
    if (!diag) {
        float* scr = smem_buf;
        #pragma unroll
        for (int half = 0; half < 2; half++) {
            __syncthreads();
            if (wc == half) {
                #pragma unroll
                for (int mt = 0; mt < 2; mt++) {
                    int m = wr * 32 + mt * 16 + lr;
                    int r1 = i0 + m;
                    float ni1 = n2[r1], ni2 = n2[r1 + 8];
                    #pragma unroll
                    for (int nt = 0; nt < 8; nt++) {
                        int nn = nt * 8 + 2 * lq;
                        int c = j0 + half * 64 + nn;
                        float njc = n2[c], njc1 = n2[c + 1];
                        scr[nn * 132 + m]           = ni1 + njc  - 2.f * acc[mt][nt][0];
                        scr[(nn + 1) * 132 + m]     = ni1 + njc1 - 2.f * acc[mt][nt][1];
                        scr[nn * 132 + m + 8]       = ni2 + njc  - 2.f * acc[mt][nt][2];
                        scr[(nn + 1) * 132 + m + 8] = ni2 + njc1 - 2.f * acc[mt][nt][3];
                    }
                }
            }
            __syncthreads();
            #pragma unroll
            for (int idx = t; idx < 64 * 128; idx += 256) {
                int nr = idx >> 7, mc = idx & 127;
                g_dist[((size_t)(b * NN + j0 + half * 64 + nr)) * NN + i0 + mc] =
                    scr[nr * 132 + mc];
            }
        }
    }
}

// ---------------- knn0: 2 rows/warp, f32 pass1 + ballot-compact pass2 --------
__global__ __launch_bounds__(256) void knn0_k() {
    __shared__ float4 pts[1024];                    // 16 KB
    __shared__ unsigned long long buf[16][128];     // 16 KB
    int t = threadIdx.x, w = t >> 5, lane = t & 31;
    int row0 = blockIdx.x * 16 + w * 2;
    int row1 = row0 + 1;
    int base = row0 & ~(NN - 1);
    float4 me0 = g_x4[row0];
    float4 me1 = g_x4[row1];

    // pass 1: per-lane top-2 per row (2 independent chains)
    float a0 = FINF, a1 = FINF;     // row0
    float b0 = FINF, b1 = FINF;     // row1
    #pragma unroll 1
    for (int chunk = 0; chunk < 4; chunk++) {
        __syncthreads();
        #pragma unroll
        for (int i = 0; i < 4; i++)
            pts[t + (i << 8)] = g_x4[base + (chunk << 10) + t + (i << 8)];
        __syncthreads();
        #pragma unroll 4
        for (int it = 0; it < 32; it++) {
            float4 p = pts[(it << 5) + lane];
            float d0 = me0.w + p.w - 2.f * (me0.x * p.x + me0.y * p.y + me0.z * p.z);
            float d1 = me1.w + p.w - 2.f * (me1.x * p.x + me1.y * p.y + me1.z * p.z);
            if (d0 < a0) { a1 = a0; a0 = d0; } else if (d0 < a1) a1 = d0;
            if (d1 < b0) { b1 = b0; b0 = d1; } else if (d1 < b1) b1 = d1;
        }
    }
    float tau0, tau1;
    {
        float v2[2] = {a0, a1};
        wsortf<2>(v2, lane);
        tau0 = __shfl_sync(FULLM, v2[0], 31);
        float v3[2] = {b0, b1};
        wsortf<2>(v3, lane);
        tau1 = __shfl_sync(FULLM, v3[0], 31);
    }

    // pass 2: ballot-compact composites for both rows
    int cnt0 = 0, cnt1 = 0;
    #pragma unroll 1
    for (int chunk = 0; chunk < 4; chunk++) {
        __syncthreads();
        #pragma unroll
        for (int i = 0; i < 4; i++)
            pts[t + (i << 8)] = g_x4[base + (chunk << 10) + t + (i << 8)];
        __syncthreads();
        #pragma unroll 4
        for (int it = 0; it < 32; it++) {
            int jl = (it << 5) + lane;
            float4 p = pts[jl];
            float d0 = me0.w + p.w - 2.f * (me0.x * p.x + me0.y * p.y + me0.z * p.z);
            float d1 = me1.w + p.w - 2.f * (me1.x * p.x + me1.y * p.y + me1.z * p.z);
            int jg = (chunk << 10) + jl;
            unsigned mask0 = __ballot_sync(FULLM, d0 <= tau0);
            if (d0 <= tau0) {
                int pos = cnt0 + __popc(mask0 & ((1u << lane) - 1));
                if (pos < 128)
                    buf[w * 2][pos] = ((unsigned long long)okey(d0) << 32) | (unsigned)jg;
            }
            cnt0 += __popc(mask0);
            unsigned mask1 = __ballot_sync(FULLM, d1 <= tau1);
            if (d1 <= tau1) {
                int pos = cnt1 + __popc(mask1 & ((1u << lane) - 1));
                if (pos < 128)
                    buf[w * 2 + 1][pos] = ((unsigned long long)okey(d1) << 32) | (unsigned)jg;
            }
            cnt1 += __popc(mask1);
        }
    }
    #pragma unroll
    for (int rr = 0; rr < 2; rr++) {
        int row = row0 + rr;
        float4 me = rr ? me1 : me0;
        int cnt = rr ? cnt1 : cnt0;
        int* out = g_idx + row * KK;
        if (!buf_finish(buf[w * 2 + rr], cnt, lane, out)) {
            // exact streaming fallback (degenerate ties)
            unsigned long long sc, tau2;
            {
                float4 p = g_x4[base + lane];
                float d = me.w + p.w - 2.f * (me.x * p.x + me.y * p.y + me.z * p.z);
                sc = ((unsigned long long)okey(d) << 32) | (unsigned)lane;
                tau2 = wmax64(sc);
            }
            for (int it = 1; it < 128; it++) {
                int j = (it << 5) + lane;
                float4 p = g_x4[base + j];
                float d = me.w + p.w - 2.f * (me.x * p.x + me.y * p.y + me.z * p.z);
                unsigned long long c = ((unsigned long long)okey(d) << 32) | (unsigned)j;
                winsert(c, sc, tau2, lane);
            }
            wfinish(sc, lane, out);
        }
    }
}

// ---------------- knn1: two-stream pass1 + ballot-compact pass2 --------------
__global__ __launch_bounds__(256) void knn1_k() {
    __shared__ unsigned long long buf[8][128];      // 8 KB
    int t = threadIdx.x, w = t >> 5, lane = t & 31;
    int row = blockIdx.x * 8 + w;
    const float4* dr = (const float4*)(g_dist + (size_t)row * NN);

    // pass 1: two independent top-2 streams per lane (A: x,y  B: z,w)
    float a0 = FINF, a1 = FINF, b0 = FINF, b1 = FINF;
    #pragma unroll 4
    for (int it = 0; it < 32; it++) {
        float4 dv = __ldg(&dr[(it << 5) + lane]);
        if (dv.x < a0) { a1 = a0; a0 = dv.x; } else if (dv.x < a1) a1 = dv.x;
        if (dv.z < b0) { b1 = b0; b0 = dv.z; } else if (dv.z < b1) b1 = dv.z;
        if (dv.y < a0) { a1 = a0; a0 = dv.y; } else if (dv.y < a1) a1 = dv.y;
        if (dv.w < b0) { b1 = b0; b0 = dv.w; } else if (dv.w < b1) b1 = dv.w;
    }
    float v4[4] = {a0, a1, b0, b1};
    wsortf<4>(v4, lane);
    float tau = __shfl_sync(FULLM, v4[0], 31);   // 32nd smallest of 128 collected

    // pass 2 (row L1-resident)
    int cnt = 0;
    #pragma unroll 2
    for (int it = 0; it < 32; it++) {
        int j4 = (it << 5) + lane;
        float4 dv = __ldg(&dr[j4]);
        int jb = j4 << 2;
        float ds[4] = {dv.x, dv.y, dv.z, dv.w};
        #pragma unroll
        for (int q = 0; q < 4; q++) {
            float d = ds[q];
            unsigned mask = __ballot_sync(FULLM, d <= tau);
            if (d <= tau) {
                int pos = cnt + __popc(mask & ((1u << lane) - 1));
                if (pos < 128)
                    buf[w][pos] = ((unsigned long long)okey(d) << 32) | (unsigned)(jb + q);
            }
            cnt += __popc(mask);
        }
    }
    int* out = g_idx + row * KK;
    if (!buf_finish(buf[w], cnt, lane, out)) {
        const float* drs = g_dist + (size_t)row * NN;
        unsigned long long sc, tau2;
        {
            sc = ((unsigned long long)okey(drs[lane]) << 32) | (unsigned)lane;
            tau2 = wmax64(sc);
        }
        for (int it = 1; it < 128; it++) {
            int j = (it << 5) + lane;
            unsigned long long c = ((unsigned long long)okey(__ldg(&drs[j])) << 32) | (unsigned)j;
            winsert(c, sc, tau2, lane);
        }
        wfinish(sc, lane, out);
    }
}

// ---------------- fused gather: BN stats + per-point neighbor vmax/vmin ------
template <int C>
__global__ __launch_bounds__(256) void gather_k() {
    constexpr int G = 256 / C;
    int t = threadIdx.x;
    int c = t % C;
    int g = t / C;
    float s = 0.f, s2 = 0.f;
    for (int p = blockIdx.x * G + g; p < NPTS; p += STATS_BLOCKS * G) {
        int b = p >> 12;
        float uc = g_u[(size_t)p * C + c];
        const int* ip = g_idx + p * KK;
        float S = 0.f, Q = 0.f, mx = -FINF, mn = FINF;
        #pragma unroll
        for (int k = 0; k < KK; k++) {
            int j = ip[k];
            float v = g_v[((size_t)((b << 12) + j)) * C + c];
            S += v;
            Q = fmaf(v, v, Q);
            mx = fmaxf(mx, v);
            mn = fminf(mn, v);
        }
        g_vmax[(size_t)p * C + c] = mx;
        g_vmin[(size_t)p * C + c] = mn;
        s += fmaf(20.f, uc, S);
        s2 += fmaf(20.f * uc, uc, fmaf(2.f * uc, S, Q));
    }
    __shared__ float sh[256], sh2[256];
    sh[t] = s; sh2[t] = s2;
    __syncthreads();
    if (t < C) {
        float S = sh[t], S2 = sh2[t];
        #pragma unroll
        for (int gg = 1; gg < G; gg++) { S += sh[gg * C + t]; S2 += sh2[gg * C + t]; }
        g_part[blockIdx.x * (2 * C) + t] = S;
        g_part[blockIdx.x * (2 * C) + C + t] = S2;
    }
}

// ---------------- finalize BN scale/shift: one block per channel -------------
template <int C>
__global__ __launch_bounds__(256) void fin_k(const float* __restrict__ gamma,
                                             const float* __restrict__ beta) {
    int c = blockIdx.x;
    int t = threadIdx.x;
    float S = 0.f, S2 = 0.f;
    #pragma unroll
    for (int bk = t; bk < STATS_BLOCKS; bk += 256) {
        S += g_part[bk * 2 * C + c];
        S2 += g_part[bk * 2 * C + C + c];
    }
    #pragma unroll
    for (int o = 16; o; o >>= 1) {
        S += __shfl_down_sync(FULLM, S, o);
        S2 += __shfl_down_sync(FULLM, S2, o);
    }
    __shared__ float sh[8], sh2[8];
    int w = t >> 5, lane = t & 31;
    if (lane == 0) { sh[w] = S; sh2[w] = S2; }
    __syncthreads();
    if (t == 0) {
        float Sa = 0.f, S2a = 0.f;
        #pragma unroll
        for (int i = 0; i < 8; i++) { Sa += sh[i]; S2a += sh2[i]; }
        const float inv = 1.f / (float)EDG;
        float mu = Sa * inv;
        float var = S2a * inv - mu * mu;
        float sc = gamma[c] * rsqrtf(var + 1e-5f);
        g_scale[c] = sc;
        g_shift[c] = beta[c] - mu * sc;
    }
}

// ---------------- finish layer0: h0 = leaky(...) ------------------------------
__global__ void finish64_k() {
    int gid = blockIdx.x * 256 + threadIdx.x;    // NPTS*64
    int c = gid & 63;
    float sc = g_scale[c];
    float vm = (sc >= 0.f) ? g_vmax[gid] : g_vmin[gid];
    float M = g_u[gid] + vm;
    g_h0[gid] = leaky(fmaf(M, sc, g_shift[c]));
}

// ---------------- finish layer1 + fused attention gate -----------------------
__global__ __launch_bounds__(256) void finish256_k(const float* __restrict__ Wg,
                                                   const float* __restrict__ bg) {
    __shared__ float sh[256];
    int p = blockIdx.x;
    int c = threadIdx.x;
    size_t gid = (size_t)p * 256 + c;
    float sc = g_scale[c];
    float vm = (sc >= 0.f) ? g_vmax[gid] : g_vmin[gid];
    float h = leaky(fmaf(g_u[gid] + vm, sc, g_shift[c]));
    g_h1[gid] = h;
    sh[c] = h * Wg[c];
    __syncthreads();
    #pragma unroll
    for (int o = 128; o; o >>= 1) {
        if (c < o) sh[c] += sh[c + o];
        __syncthreads();
    }
    if (c == 0) {
        float gg = sh[0] + bg[0];
        g_gate[p] = gg > 0.f ? gg : 0.f;
    }
}

__global__ void softmax_k() {
    int b = blockIdx.x, t = threadIdx.x;
    __shared__ float sh[256];
    const float* gp = g_gate + (b << 12);
    float* ap = g_alpha + (b << 12);
    float mx = -FINF;
    for (int s = 0; s < 16; s++) mx = fmaxf(mx, gp[t + (s << 8)]);
    sh[t] = mx; __syncthreads();
    for (int o = 128; o; o >>= 1) { if (t < o) sh[t] = fmaxf(sh[t], sh[t + o]); __syncthreads(); }
    float M = sh[0];
    __syncthreads();
    float sum = 0.f;
    for (int s = 0; s < 16; s++) {
        int j = t + (s << 8);
        float e = expf(gp[j] - M);
        ap[j] = e;
        sum += e;
    }
    sh[t] = sum; __syncthreads();
    for (int o = 128; o; o >>= 1) { if (t < o) sh[t] += sh[t + o]; __syncthreads(); }
    float inv = 1.f / sh[0];
    for (int s = 0; s < 16; s++) ap[t + (s << 8)] *= inv;
}

// ---------------- tf32 tensor-core feat GEMM + weighted pooling ---------------
__global__ __launch_bounds__(256) void pool_tc_k(const float* __restrict__ Wf,
                                                 const float* __restrict__ bf) {
    __shared__ float Ah[128][36];
    __shared__ float Bw[128][33];
    __shared__ float als[128];
    __shared__ float part[8][64];
    const int nblk = blockIdx.x, chblk = blockIdx.y, b = blockIdx.z;
    const int n0 = nblk * 128, ch0 = chblk * 128;
    int t = threadIdx.x;
    int w = t >> 5, lane = t & 31;
    int wr = w >> 1, wc = w & 1;
    int lq = lane & 3, lr = lane >> 2;

    if (t < 128) als[t] = g_alpha[(b << 12) + n0 + t];

    float acc[2][8][4];
    #pragma unroll
    for (int mt = 0; mt < 2; mt++)
        #pragma unroll
        for (int nt = 0; nt < 8; nt++)
            #pragma unroll
            for (int q = 0; q < 4; q++) acc[mt][nt][q] = 0.f;

    #pragma unroll 1
    for (int kc = 0; kc < 8; kc++) {
        __syncthreads();
        #pragma unroll
        for (int idx = t; idx < 128 * 8; idx += 256) {
            int r = idx >> 3, c4 = (idx & 7) << 2;
            float4 va = *(const float4*)&g_h1[((size_t)((b << 12) + n0 + r)) * 256 + kc * 32 + c4];
            *(float4*)&Ah[r][c4] = make_float4(tf32r(va.x), tf32r(va.y), tf32r(va.z), tf32r(va.w));
        }
        #pragma unroll
        for (int idx = t; idx < 128 * 32; idx += 256) {
            int c = idx & 127, dd = idx >> 7;
            Bw[c][dd] = tf32r(Wf[(size_t)(kc * 32 + dd) * 512 + ch0 + c]);
        }
        __syncthreads();
        #pragma unroll
        for (int ks = 0; ks < 4; ks++) {
            int kk = ks * 8;
            unsigned af[2][4], bfr[8][2];
            #pragma unroll
            for (int mt = 0; mt < 2; mt++) {
                int ar = wr * 32 + mt * 16 + lr;
                af[mt][0] = __float_as_uint(Ah[ar][kk + lq]);
                af[mt][1] = __float_as_uint(Ah[ar + 8][kk + lq]);
                af[mt][2] = __float_as_uint(Ah[ar][kk + lq + 4]);
                af[mt][3] = __float_as_uint(Ah[ar + 8][kk + lq + 4]);
            }
            #pragma unroll
            for (int nt = 0; nt < 8; nt++) {
                int bn = wc * 64 + nt * 8 + lr;
                bfr[nt][0] = __float_as_uint(Bw[bn][kk + lq]);
                bfr[nt][1] = __float_as_uint(Bw[bn][kk + lq + 4]);
            }
            #pragma unroll
            for (int mt = 0; mt < 2; mt++)
                #pragma unroll
                for (int nt = 0; nt < 8; nt++)
                    mma_tf32(acc[mt][nt], af[mt], bfr[nt]);
        }
    }
    __syncthreads();

    #pragma unroll
    for (int nt = 0; nt < 8; nt++) {
        int cE = wc * 64 + nt * 8 + 2 * lq;
        float bfe = __ldg(&bf[ch0 + cE]);
        float bfo = __ldg(&bf[ch0 + cE + 1]);
        float se = 0.f, so = 0.f;
        #pragma unroll
        for (int mt = 0; mt < 2; mt++) {
            int rloc = wr * 32 + mt * 16 + lr;
            float a1 = als[rloc], a2 = als[rloc + 8];
            float f0 = acc[mt][nt][0] + bfe; f0 = f0 > 0.f ? f0 : 0.f;
            float f1 = acc[mt][nt][1] + bfo; f1 = f1 > 0.f ? f1 : 0.f;
            float f2 = acc[mt][nt][2] + bfe; f2 = f2 > 0.f ? f2 : 0.f;
            float f3 = acc[mt][nt][3] + bfo; f3 = f3 > 0.f ? f3 : 0.f;
            se = fmaf(a1, f0, fmaf(a2, f2, se));
            so = fmaf(a1, f1, fmaf(a2, f3, so));
        }
        #pragma unroll
        for (int o = 4; o < 32; o <<= 1) {
            se += __shfl_xor_sync(FULLM, se, o);
            so += __shfl_xor_sync(FULLM, so, o);
        }
        if (lr == 0) {
            part[w][nt * 8 + 2 * lq] = se;
            part[w][nt * 8 + 2 * lq + 1] = so;
        }
    }
    __syncthreads();
    if (t < 128) {
        int cg = t >> 6;
        int cl = t & 63;
        float s = part[0 * 2 + cg][cl] + part[1 * 2 + cg][cl]
                + part[2 * 2 + cg][cl] + part[3 * 2 + cg][cl];
        g_pool[((nblk << 2) + b) * 512 + ch0 + t] = s;
    }
}

__global__ void poolred_k() {
    int gid = blockIdx.x * 256 + threadIdx.x;  // BB*512
    if (gid >= BB * 512) return;
    int b = gid >> 9, ch = gid & 511;
    float s = 0.f;
    for (int sl = 0; sl < 32; sl++) s += g_pool[((sl << 2) + b) * 512 + ch];
    g_pooled[gid] = s;
}

__global__ void final_k(const float* __restrict__ Wl, const float* __restrict__ bl,
                        float* __restrict__ out) {
    int b = blockIdx.x, o = threadIdx.x;
    const float* p = g_pooled + b * 512;
    float s = bl[o];
    #pragma unroll 8
    for (int f = 0; f < 512; f++) s = fmaf(p[f], Wl[f * 256 + o], s);
    out[b * 256 + o] = s;
}

// ---------------- launch ------------------------------------------------------
extern "C" void kernel_launch(void* const* d_in, const int* in_sizes, int n_in,
                              void* d_out, int out_size) {
    (void)in_sizes; (void)n_in; (void)out_size;
    const float* x   = (const float*)d_in[0];
    const float* Wt0 = (const float*)d_in[1];
    const float* Wp0 = (const float*)d_in[3];
    const float* g0  = (const float*)d_in[5];
    const float* be0 = (const float*)d_in[6];
    const float* Wt1 = (const float*)d_in[7];
    const float* Wp1 = (const float*)d_in[9];
    const float* g1  = (const float*)d_in[11];
    const float* be1 = (const float*)d_in[12];
    const float* Wg  = (const float*)d_in[13];
    const float* bg  = (const float*)d_in[14];
    const float* Wf  = (const float*)d_in[15];
    const float* bf  = (const float*)d_in[16];
    const float* Wl  = (const float*)d_in[17];
    const float* bl  = (const float*)d_in[18];
    float* out = (float*)d_out;

    // ---- layer 0 ----
    init_k<<<NPTS * 64 / 256, 256>>>(x, Wt0, Wp0, Wt1, Wp1);
    knn0_k<<<NPTS / 16, 256>>>();
    gather_k<64><<<STATS_BLOCKS, 256>>>();
    fin_k<64><<<64, 256>>>(g0, be0);
    finish64_k<<<NPTS * 64 / 256, 256>>>();

    // ---- layer 1 ----
    gemm16_k<<<NPTS / 16, 256>>>(Wt1);
    dist_tc_k<<<dim3(528, BB), 256>>>();
    knn1_k<<<NPTS / 8, 256>>>();
    gather_k<256><<<STATS_BLOCKS, 256>>>();
    fin_k<256><<<256, 256>>>(g1, be1);
    finish256_k<<<NPTS, 256>>>(Wg, bg);

    // ---- attention pooling + final linear ----
    softmax_k<<<BB, 256>>>();
    pool_tc_k<<<dim3(32, 4, BB), 256>>>(Wf, bf);
    poolred_k<<<8, 256>>>();
    final_k<<<BB, 256>>>(Wl, bl, out);
}